// round 1
// baseline (speedup 1.0000x reference)
#include <cuda_runtime.h>
#include <math.h>

#define Bz 4
#define Tz 2048
#define Cz 1024
#define Hz 16
#define HDz 64
#define Mz (Bz * Tz)

// Scratch (static __device__ — no allocations allowed).
// q,k,v laid out [B*H, T, hd] so K/V tile loads in attention are contiguous.
__device__ float g_q[(size_t)Bz * Hz * Tz * HDz];
__device__ float g_k[(size_t)Bz * Hz * Tz * HDz];
__device__ float g_v[(size_t)Bz * Hz * Tz * HDz];
// attention output in [B, T, C] layout (input to proj GEMM)
__device__ float g_att[(size_t)Mz * Cz];

// ---------------------------------------------------------------------------
// QKV GEMM: [8192,1024] @ [1024,3072] + bias, scattered into g_q/g_k/g_v
// 128x128 block tile, 256 threads, 8x8 per-thread micro-tile, K-tile = 8.
// ---------------------------------------------------------------------------
__global__ __launch_bounds__(256) void qkv_gemm(const float* __restrict__ X,
                                                const float* __restrict__ W,
                                                const float* __restrict__ bias) {
    const int K = Cz;
    const int N = 3 * Cz;
    __shared__ float As[8][128];
    __shared__ float Bs[8][128];
    int n0 = blockIdx.x * 128;
    int m0 = blockIdx.y * 128;
    int tid = threadIdx.x;
    int tx = tid & 15, ty = tid >> 4;
    float acc[8][8];
#pragma unroll
    for (int i = 0; i < 8; i++)
#pragma unroll
        for (int j = 0; j < 8; j++) acc[i][j] = 0.0f;

    for (int k0 = 0; k0 < K; k0 += 8) {
        // A tile: 128 rows x 8 cols (transposed store)
        int ar = tid >> 1;
        int ac = (tid & 1) * 4;
        float4 av = *reinterpret_cast<const float4*>(&X[(m0 + ar) * K + k0 + ac]);
        As[ac + 0][ar] = av.x;
        As[ac + 1][ar] = av.y;
        As[ac + 2][ar] = av.z;
        As[ac + 3][ar] = av.w;
        // B tile: 8 rows x 128 cols, coalesced float4
        int bi = tid * 4;
        int br = bi >> 7, bc = bi & 127;
        *reinterpret_cast<float4*>(&Bs[br][bc]) =
            *reinterpret_cast<const float4*>(&W[(k0 + br) * N + n0 + bc]);
        __syncthreads();
#pragma unroll
        for (int kk = 0; kk < 8; kk++) {
            float a_frag[8], b_frag[8];
#pragma unroll
            for (int i = 0; i < 8; i++) a_frag[i] = As[kk][ty * 8 + i];
#pragma unroll
            for (int j = 0; j < 8; j++) b_frag[j] = Bs[kk][tx * 8 + j];
#pragma unroll
            for (int i = 0; i < 8; i++)
#pragma unroll
                for (int j = 0; j < 8; j++) acc[i][j] += a_frag[i] * b_frag[j];
        }
        __syncthreads();
    }

    // Epilogue: add bias, scatter into q/k/v with [B*H, T, hd] layout
#pragma unroll
    for (int i = 0; i < 8; i++) {
        int m = m0 + ty * 8 + i;
        int b = m / Tz;
        int t = m - b * Tz;
#pragma unroll
        for (int j = 0; j < 8; j++) {
            int n = n0 + tx * 8 + j;
            float val = acc[i][j] + bias[n];
            int which = n / Cz;           // 0=q, 1=k, 2=v
            int c = n - which * Cz;
            int h = c >> 6;
            int d = c & 63;
            float* dst = (which == 0) ? g_q : (which == 1) ? g_k : g_v;
            dst[(((b * Hz + h) * Tz) + t) * HDz + d] = val;
        }
    }
}

// ---------------------------------------------------------------------------
// Flash attention (fp32): one CTA = 128 query rows of one (b,h).
// Each thread owns one query: q[64], o[64] in regs, online softmax.
// K/V tiles (32x64 each) staged in shared memory.
// ---------------------------------------------------------------------------
__global__ __launch_bounds__(128) void attn_kernel() {
    __shared__ float Ks[32][64];
    __shared__ float Vs[32][64];

    int bh = blockIdx.y;                 // 0..63
    int q0 = blockIdx.x * 128;
    int tid = threadIdx.x;
    int qidx = q0 + tid;

    const float* qptr = g_q + ((size_t)bh * Tz + qidx) * HDz;
    float q[64];
#pragma unroll
    for (int i = 0; i < 16; i++) {
        float4 v = reinterpret_cast<const float4*>(qptr)[i];
        q[i * 4 + 0] = v.x;
        q[i * 4 + 1] = v.y;
        q[i * 4 + 2] = v.z;
        q[i * 4 + 3] = v.w;
    }

    float mval = -INFINITY;
    float lval = 0.0f;
    float o[64];
#pragma unroll
    for (int d = 0; d < 64; d++) o[d] = 0.0f;

    const float scale = 0.125f;  // 1/sqrt(64)

    for (int k0 = 0; k0 < q0 + 128; k0 += 32) {
        const float* kbase = g_k + ((size_t)bh * Tz + k0) * HDz;
        const float* vbase = g_v + ((size_t)bh * Tz + k0) * HDz;
        // 32x64 = 2048 floats each; 128 threads x 4 float4
#pragma unroll
        for (int i = 0; i < 4; i++) {
            int f = tid + i * 128;     // float4 index 0..511
            int off = f * 4;
            int row = off >> 6;
            int col = off & 63;
            *reinterpret_cast<float4*>(&Ks[row][col]) =
                *reinterpret_cast<const float4*>(&kbase[off]);
            *reinterpret_cast<float4*>(&Vs[row][col]) =
                *reinterpret_cast<const float4*>(&vbase[off]);
        }
        __syncthreads();

#pragma unroll 1
        for (int j = 0; j < 32; j++) {
            int kk = k0 + j;
            float s = 0.0f;
#pragma unroll
            for (int dv = 0; dv < 16; dv++) {
                float4 kv = *reinterpret_cast<const float4*>(&Ks[j][dv * 4]);
                s += q[dv * 4 + 0] * kv.x;
                s += q[dv * 4 + 1] * kv.y;
                s += q[dv * 4 + 2] * kv.z;
                s += q[dv * 4 + 3] * kv.w;
            }
            s *= scale;
            if (kk > qidx) s = -INFINITY;   // causal mask
            if (s > mval) {
                float corr = __expf(mval - s);
                mval = s;
                lval *= corr;
#pragma unroll
                for (int d = 0; d < 64; d++) o[d] *= corr;
            }
            float p = __expf(s - mval);     // 0 for masked keys
            lval += p;
#pragma unroll
            for (int dv = 0; dv < 16; dv++) {
                float4 vv = *reinterpret_cast<const float4*>(&Vs[j][dv * 4]);
                o[dv * 4 + 0] += p * vv.x;
                o[dv * 4 + 1] += p * vv.y;
                o[dv * 4 + 2] += p * vv.z;
                o[dv * 4 + 3] += p * vv.w;
            }
        }
        __syncthreads();
    }

    float inv = 1.0f / lval;
    int b = bh >> 4;
    int h = bh & 15;
    float* yp = g_att + ((size_t)b * Tz + qidx) * Cz + h * HDz;
#pragma unroll
    for (int i = 0; i < 16; i++) {
        float4 v;
        v.x = o[i * 4 + 0] * inv;
        v.y = o[i * 4 + 1] * inv;
        v.z = o[i * 4 + 2] * inv;
        v.w = o[i * 4 + 3] * inv;
        reinterpret_cast<float4*>(yp)[i] = v;
    }
}

// ---------------------------------------------------------------------------
// Output projection: g_att [8192,1024] @ W_proj [1024,1024] + b_proj -> d_out
// ---------------------------------------------------------------------------
__global__ __launch_bounds__(256) void proj_gemm(const float* __restrict__ W,
                                                 const float* __restrict__ bias,
                                                 float* __restrict__ out) {
    const int K = Cz;
    const int N = Cz;
    __shared__ float As[8][128];
    __shared__ float Bs[8][128];
    int n0 = blockIdx.x * 128;
    int m0 = blockIdx.y * 128;
    int tid = threadIdx.x;
    int tx = tid & 15, ty = tid >> 4;
    float acc[8][8];
#pragma unroll
    for (int i = 0; i < 8; i++)
#pragma unroll
        for (int j = 0; j < 8; j++) acc[i][j] = 0.0f;

    for (int k0 = 0; k0 < K; k0 += 8) {
        int ar = tid >> 1;
        int ac = (tid & 1) * 4;
        float4 av = *reinterpret_cast<const float4*>(&g_att[(size_t)(m0 + ar) * K + k0 + ac]);
        As[ac + 0][ar] = av.x;
        As[ac + 1][ar] = av.y;
        As[ac + 2][ar] = av.z;
        As[ac + 3][ar] = av.w;
        int bi = tid * 4;
        int br = bi >> 7, bc = bi & 127;
        *reinterpret_cast<float4*>(&Bs[br][bc]) =
            *reinterpret_cast<const float4*>(&W[(k0 + br) * N + n0 + bc]);
        __syncthreads();
#pragma unroll
        for (int kk = 0; kk < 8; kk++) {
            float a_frag[8], b_frag[8];
#pragma unroll
            for (int i = 0; i < 8; i++) a_frag[i] = As[kk][ty * 8 + i];
#pragma unroll
            for (int j = 0; j < 8; j++) b_frag[j] = Bs[kk][tx * 8 + j];
#pragma unroll
            for (int i = 0; i < 8; i++)
#pragma unroll
                for (int j = 0; j < 8; j++) acc[i][j] += a_frag[i] * b_frag[j];
        }
        __syncthreads();
    }

#pragma unroll
    for (int i = 0; i < 8; i++) {
        int m = m0 + ty * 8 + i;
#pragma unroll
        for (int j = 0; j < 8; j++) {
            int n = n0 + tx * 8 + j;
            out[(size_t)m * N + n] = acc[i][j] + bias[n];
        }
    }
}

// ---------------------------------------------------------------------------
extern "C" void kernel_launch(void* const* d_in, const int* in_sizes, int n_in,
                              void* d_out, int out_size) {
    const float* x      = (const float*)d_in[0];  // [4,2048,1024]
    const float* W_attn = (const float*)d_in[1];  // [1024,3072]
    const float* b_attn = (const float*)d_in[2];  // [3072]
    const float* W_proj = (const float*)d_in[3];  // [1024,1024]
    const float* b_proj = (const float*)d_in[4];  // [1024]
    float* out = (float*)d_out;                   // [4,2048,1024]

    (void)in_sizes; (void)n_in; (void)out_size;

    // QKV GEMM: M=8192, N=3072
    dim3 g1(3 * Cz / 128, Mz / 128);
    qkv_gemm<<<g1, 256>>>(x, W_attn, b_attn);

    // Flash attention: 16 q-tiles x 64 (b,h) pairs
    dim3 g2(Tz / 128, Bz * Hz);
    attn_kernel<<<g2, 128>>>();

    // Projection: M=8192, N=1024
    dim3 g3(Cz / 128, Mz / 128);
    proj_gemm<<<g3, 256>>>(W_proj, b_proj, out);
}

// round 3
// speedup vs baseline: 1.7998x; 1.7998x over previous
#include <cuda_runtime.h>
#include <cuda_fp16.h>
#include <math.h>
#include <stdint.h>

#define Bz 4
#define Tz 2048
#define Cz 1024
#define Hz 16
#define HDz 64
#define Mz (Bz * Tz)

// ---------------- scratch (static __device__; no allocations allowed) -------
__device__ float g_q[(size_t)Bz * Hz * Tz * HDz];
__device__ float g_k[(size_t)Bz * Hz * Tz * HDz];
__device__ float g_v[(size_t)Bz * Hz * Tz * HDz];
__device__ __half g_xh[(size_t)Mz * Cz];        // x in fp16 [M,K] row-major
__device__ __half g_wat[(size_t)3 * Cz * Cz];   // W_attn^T fp16 [N=3072][K=1024]
__device__ __half g_wpt[(size_t)Cz * Cz];       // W_proj^T fp16 [N=1024][K=1024]
__device__ __half g_att_h[(size_t)Mz * Cz];     // attention out fp16 [M,C]

// ---------------- helpers ----------------------------------------------------
static __device__ __forceinline__ uint32_t s2u(const void* p) {
    uint32_t a;
    asm("{ .reg .u64 t; cvta.to.shared.u64 t, %1; cvt.u32.u64 %0, t; }"
        : "=r"(a) : "l"(p));
    return a;
}

static __device__ __forceinline__ void cpa16(uint32_t dst, const void* src) {
    asm volatile("cp.async.cg.shared.global [%0], [%1], 16;"
                 :: "r"(dst), "l"(__cvta_generic_to_global(src)));
}

static __device__ __forceinline__ void ldm4(uint32_t* r, uint32_t addr) {
    asm volatile("ldmatrix.sync.aligned.m8n8.x4.shared.b16 {%0,%1,%2,%3}, [%4];"
                 : "=r"(r[0]), "=r"(r[1]), "=r"(r[2]), "=r"(r[3]) : "r"(addr));
}

static __device__ __forceinline__ void mma16816(float* c, const uint32_t* a,
                                                const uint32_t* b) {
    asm volatile(
        "mma.sync.aligned.m16n8k16.row.col.f32.f16.f16.f32 "
        "{%0,%1,%2,%3}, {%4,%5,%6,%7}, {%8,%9}, {%0,%1,%2,%3};"
        : "+f"(c[0]), "+f"(c[1]), "+f"(c[2]), "+f"(c[3])
        : "r"(a[0]), "r"(a[1]), "r"(a[2]), "r"(a[3]), "r"(b[0]), "r"(b[1]));
}

// ---------------- conversion kernels ----------------------------------------
__global__ void conv_x_kernel(const float4* __restrict__ x, uint2* __restrict__ xh, int n4) {
    int i = blockIdx.x * blockDim.x + threadIdx.x;
    if (i < n4) {
        float4 v = x[i];
        __half2 h0 = __floats2half2_rn(v.x, v.y);
        __half2 h1 = __floats2half2_rn(v.z, v.w);
        uint2 u;
        u.x = *reinterpret_cast<uint32_t*>(&h0);
        u.y = *reinterpret_cast<uint32_t*>(&h1);
        xh[i] = u;
    }
}

// W [R rows][C cols] fp32 -> Wt [C][R] fp16
__global__ void convT_kernel(const float* __restrict__ W, __half* __restrict__ Wt,
                             int R, int C) {
    __shared__ float t[32][33];
    int c0 = blockIdx.x * 32, r0 = blockIdx.y * 32;
    int tx = threadIdx.x, ty = threadIdx.y;  // 32 x 8
#pragma unroll
    for (int i = 0; i < 4; i++)
        t[ty + i * 8][tx] = W[(size_t)(r0 + ty + i * 8) * C + c0 + tx];
    __syncthreads();
#pragma unroll
    for (int i = 0; i < 4; i++)
        Wt[(size_t)(c0 + ty + i * 8) * R + r0 + tx] = __float2half_rn(t[tx][ty + i * 8]);
}

// ---------------- mma.sync fp16 GEMM -----------------------------------------
// D[128,128] CTA tile = A[M,K] @ B[N,K]^T.  K=1024, chunk=32, double-buffered
// cp.async.  8 warps: warp_m = wid&3 (32 rows), warp_n = wid>>2 (64 cols).
// mode 0: scatter into g_q/g_k/g_v (fp32).  mode 1: write fp32 out [M,N].

#define STRIDE_H 40   // halves per smem row (32 data + 8 pad); 80 bytes

__global__ __launch_bounds__(256) void gemm_mma(
    const __half* __restrict__ Ah, const __half* __restrict__ Bh,
    const float* __restrict__ bias, float* __restrict__ out,
    int N, int mode) {
    __shared__ __align__(16) __half sA[2][128 * STRIDE_H];
    __shared__ __align__(16) __half sB[2][128 * STRIDE_H];

    const int tid = threadIdx.x;
    const int wid = tid >> 5, lane = tid & 31;
    const int warp_m = wid & 3, warp_n = wid >> 2;
    const int m0 = blockIdx.y * 128, n0 = blockIdx.x * 128;

    const uint32_t sa[2] = { s2u(sA[0]), s2u(sA[1]) };
    const uint32_t sbm[2] = { s2u(sB[0]), s2u(sB[1]) };

    float acc[2][8][4];
#pragma unroll
    for (int mi = 0; mi < 2; mi++)
#pragma unroll
        for (int ni = 0; ni < 8; ni++)
#pragma unroll
            for (int c = 0; c < 4; c++) acc[mi][ni][c] = 0.0f;

    // per-thread load indices: 512 16B chunks per tile, 2 per thread
    const int r0i = tid >> 2, c0i = tid & 3;           // chunk idx tid
    const int r1i = (tid + 256) >> 2, c1i = tid & 3;   // chunk idx tid+256

    // A-frag ldmatrix address components (row within tile, byte col base)
    const int a_row = warp_m * 32 + (lane & 15);
    const int a_kb = (lane >> 4) * 16;                 // byte offset within kstep
    // B-frag: row = warp_n*64 + ni2*16 + (lane&7) + ((lane&16)?8:0)
    const int b_row_base = warp_n * 64 + (lane & 7) + ((lane & 16) ? 8 : 0);
    const int b_kb = (lane & 8) ? 16 : 0;

    // prologue: chunk 0 -> buf 0
    {
        cpa16(sa[0] + r0i * 80 + c0i * 16, Ah + (size_t)(m0 + r0i) * 1024 + c0i * 8);
        cpa16(sbm[0] + r0i * 80 + c0i * 16, Bh + (size_t)(n0 + r0i) * 1024 + c0i * 8);
        cpa16(sa[0] + r1i * 80 + c1i * 16, Ah + (size_t)(m0 + r1i) * 1024 + c1i * 8);
        cpa16(sbm[0] + r1i * 80 + c1i * 16, Bh + (size_t)(n0 + r1i) * 1024 + c1i * 8);
        asm volatile("cp.async.commit_group;");
    }

#pragma unroll 1
    for (int kc = 0; kc < 32; kc++) {
        const int cur = kc & 1;
        if (kc < 31) {
            const int nb = cur ^ 1;
            const int k0 = (kc + 1) * 32;
            cpa16(sa[nb] + r0i * 80 + c0i * 16, Ah + (size_t)(m0 + r0i) * 1024 + k0 + c0i * 8);
            cpa16(sbm[nb] + r0i * 80 + c0i * 16, Bh + (size_t)(n0 + r0i) * 1024 + k0 + c0i * 8);
            cpa16(sa[nb] + r1i * 80 + c1i * 16, Ah + (size_t)(m0 + r1i) * 1024 + k0 + c1i * 8);
            cpa16(sbm[nb] + r1i * 80 + c1i * 16, Bh + (size_t)(n0 + r1i) * 1024 + k0 + c1i * 8);
            asm volatile("cp.async.commit_group;");
            asm volatile("cp.async.wait_group 1;");
        } else {
            asm volatile("cp.async.wait_group 0;");
        }
        __syncthreads();

#pragma unroll
        for (int ks = 0; ks < 2; ks++) {
            const int kb = ks * 32;   // byte offset of kstep within 64B row data
            uint32_t a[2][4];
#pragma unroll
            for (int mi = 0; mi < 2; mi++)
                ldm4(a[mi], sa[cur] + (a_row + mi * 16) * 80 + kb + a_kb);
            uint32_t b[8][2];
#pragma unroll
            for (int ni2 = 0; ni2 < 4; ni2++) {
                uint32_t r[4];
                ldm4(r, sbm[cur] + (b_row_base + ni2 * 16) * 80 + kb + b_kb);
                b[ni2 * 2 + 0][0] = r[0]; b[ni2 * 2 + 0][1] = r[1];
                b[ni2 * 2 + 1][0] = r[2]; b[ni2 * 2 + 1][1] = r[3];
            }
#pragma unroll
            for (int mi = 0; mi < 2; mi++)
#pragma unroll
                for (int ni = 0; ni < 8; ni++)
                    mma16816(acc[mi][ni], a[mi], b[ni]);
        }
        __syncthreads();
    }

    // epilogue: c-frag -> global (+bias), float2 per pair
    const int rbase = warp_m * 32 + (lane >> 2);
    const int cbase = warp_n * 64 + (lane & 3) * 2;
#pragma unroll
    for (int mi = 0; mi < 2; mi++) {
#pragma unroll
        for (int ni = 0; ni < 8; ni++) {
            const int n = n0 + cbase + ni * 8;
            const float2 bsv = *reinterpret_cast<const float2*>(&bias[n]);
#pragma unroll
            for (int hh = 0; hh < 2; hh++) {
                const int m = m0 + rbase + mi * 16 + hh * 8;
                float2 v;
                v.x = acc[mi][ni][hh * 2 + 0] + bsv.x;
                v.y = acc[mi][ni][hh * 2 + 1] + bsv.y;
                if (mode == 0) {
                    const int which = n >> 10;
                    const int ci = n & 1023;
                    const int h = ci >> 6, d = ci & 63;
                    const int b = m >> 11, t = m & 2047;
                    float* dst = (which == 0) ? g_q : (which == 1) ? g_k : g_v;
                    *reinterpret_cast<float2*>(
                        &dst[(((size_t)b * Hz + h) * Tz + t) * HDz + d]) = v;
                } else {
                    *reinterpret_cast<float2*>(&out[(size_t)m * N + n]) = v;
                }
            }
        }
    }
}

// ---------------- flash attention (fp32; fp16 output) ------------------------
__global__ __launch_bounds__(128) void attn_kernel() {
    __shared__ float Ks[32][64];
    __shared__ float Vs[32][64];

    int bh = blockIdx.y;
    int q0 = blockIdx.x * 128;
    int tid = threadIdx.x;
    int qidx = q0 + tid;

    const float* qptr = g_q + ((size_t)bh * Tz + qidx) * HDz;
    float q[64];
#pragma unroll
    for (int i = 0; i < 16; i++) {
        float4 v = reinterpret_cast<const float4*>(qptr)[i];
        q[i * 4 + 0] = v.x; q[i * 4 + 1] = v.y;
        q[i * 4 + 2] = v.z; q[i * 4 + 3] = v.w;
    }

    float mval = -INFINITY, lval = 0.0f;
    float o[64];
#pragma unroll
    for (int d = 0; d < 64; d++) o[d] = 0.0f;

    const float scale = 0.125f;

    for (int k0 = 0; k0 < q0 + 128; k0 += 32) {
        const float* kbase = g_k + ((size_t)bh * Tz + k0) * HDz;
        const float* vbase = g_v + ((size_t)bh * Tz + k0) * HDz;
#pragma unroll
        for (int i = 0; i < 4; i++) {
            int f = tid + i * 128;
            int off = f * 4;
            int row = off >> 6, col = off & 63;
            *reinterpret_cast<float4*>(&Ks[row][col]) =
                *reinterpret_cast<const float4*>(&kbase[off]);
            *reinterpret_cast<float4*>(&Vs[row][col]) =
                *reinterpret_cast<const float4*>(&vbase[off]);
        }
        __syncthreads();

#pragma unroll 1
        for (int j = 0; j < 32; j++) {
            int kk = k0 + j;
            float s = 0.0f;
#pragma unroll
            for (int dv = 0; dv < 16; dv++) {
                float4 kv = *reinterpret_cast<const float4*>(&Ks[j][dv * 4]);
                s += q[dv * 4 + 0] * kv.x;
                s += q[dv * 4 + 1] * kv.y;
                s += q[dv * 4 + 2] * kv.z;
                s += q[dv * 4 + 3] * kv.w;
            }
            s *= scale;
            if (kk > qidx) s = -INFINITY;
            if (s > mval) {
                float corr = __expf(mval - s);
                mval = s;
                lval *= corr;
#pragma unroll
                for (int d = 0; d < 64; d++) o[d] *= corr;
            }
            float p = __expf(s - mval);
            lval += p;
#pragma unroll
            for (int dv = 0; dv < 16; dv++) {
                float4 vv = *reinterpret_cast<const float4*>(&Vs[j][dv * 4]);
                o[dv * 4 + 0] += p * vv.x;
                o[dv * 4 + 1] += p * vv.y;
                o[dv * 4 + 2] += p * vv.z;
                o[dv * 4 + 3] += p * vv.w;
            }
        }
        __syncthreads();
    }

    float inv = 1.0f / lval;
    int b = bh >> 4, h = bh & 15;
    __half* yp = g_att_h + ((size_t)b * Tz + qidx) * Cz + h * HDz;
#pragma unroll
    for (int i = 0; i < 32; i++) {
        __half2 hv = __floats2half2_rn(o[2 * i] * inv, o[2 * i + 1] * inv);
        reinterpret_cast<__half2*>(yp)[i] = hv;
    }
}

// ---------------------------------------------------------------------------
extern "C" void kernel_launch(void* const* d_in, const int* in_sizes, int n_in,
                              void* d_out, int out_size) {
    const float* x      = (const float*)d_in[0];  // [4,2048,1024]
    const float* W_attn = (const float*)d_in[1];  // [1024,3072]
    const float* b_attn = (const float*)d_in[2];  // [3072]
    const float* W_proj = (const float*)d_in[3];  // [1024,1024]
    const float* b_proj = (const float*)d_in[4];  // [1024]
    float* out = (float*)d_out;
    (void)in_sizes; (void)n_in; (void)out_size;

    __half* xh;  cudaGetSymbolAddress((void**)&xh,  g_xh);
    __half* wat; cudaGetSymbolAddress((void**)&wat, g_wat);
    __half* wpt; cudaGetSymbolAddress((void**)&wpt, g_wpt);
    __half* ath; cudaGetSymbolAddress((void**)&ath, g_att_h);

    // fp16 conversions
    {
        int n4 = Mz * Cz / 4;
        conv_x_kernel<<<(n4 + 255) / 256, 256>>>((const float4*)x, (uint2*)xh, n4);
        dim3 g(3 * Cz / 32, Cz / 32);
        convT_kernel<<<g, dim3(32, 8)>>>(W_attn, wat, Cz, 3 * Cz);
        dim3 g2(Cz / 32, Cz / 32);
        convT_kernel<<<g2, dim3(32, 8)>>>(W_proj, wpt, Cz, Cz);
    }

    // QKV GEMM: M=8192, N=3072
    dim3 g1(3 * Cz / 128, Mz / 128);
    gemm_mma<<<g1, 256>>>(xh, wat, b_attn, nullptr, 3 * Cz, 0);

    // Flash attention
    dim3 g2(Tz / 128, Bz * Hz);
    attn_kernel<<<g2, 128>>>();

    // Projection: M=8192, N=1024
    dim3 g3(Cz / 128, Mz / 128);
    gemm_mma<<<g3, 256>>>(ath, wpt, b_proj, out, Cz, 1);
}

// round 4
// speedup vs baseline: 7.5841x; 4.2140x over previous
#include <cuda_runtime.h>
#include <cuda_fp16.h>
#include <math.h>
#include <stdint.h>

#define Bz 4
#define Tz 2048
#define Cz 1024
#define Hz 16
#define HDz 64
#define Mz (Bz * Tz)

// scale folded into q: 1/sqrt(64) * log2(e)  (softmax done in base-2)
#define QSCALE 0.1803368801111204f

// ---------------- scratch (static __device__; no allocations allowed) -------
__device__ __half g_qh[(size_t)Bz * Hz * Tz * HDz];   // [BH][T][64] fp16 (pre-scaled)
__device__ __half g_kh[(size_t)Bz * Hz * Tz * HDz];   // [BH][T][64] fp16
__device__ __half g_vh[(size_t)Bz * Hz * Tz * HDz];   // [BH][T][64] fp16
__device__ __half g_xh[(size_t)Mz * Cz];              // x fp16 [M,K]
__device__ __half g_wat[(size_t)3 * Cz * Cz];         // W_attn^T fp16 [3072][1024]
__device__ __half g_wpt[(size_t)Cz * Cz];             // W_proj^T fp16 [1024][1024]
__device__ __half g_att_h[(size_t)Mz * Cz];           // attn out fp16 [M,C]

// ---------------- helpers ----------------------------------------------------
static __device__ __forceinline__ uint32_t s2u(const void* p) {
    uint32_t a;
    asm("{ .reg .u64 t; cvta.to.shared.u64 t, %1; cvt.u32.u64 %0, t; }"
        : "=r"(a) : "l"(p));
    return a;
}

static __device__ __forceinline__ void cpa16(uint32_t dst, const void* src) {
    asm volatile("cp.async.cg.shared.global [%0], [%1], 16;"
                 :: "r"(dst), "l"(__cvta_generic_to_global(src)));
}

static __device__ __forceinline__ void ldm4(uint32_t* r, uint32_t addr) {
    asm volatile("ldmatrix.sync.aligned.m8n8.x4.shared.b16 {%0,%1,%2,%3}, [%4];"
                 : "=r"(r[0]), "=r"(r[1]), "=r"(r[2]), "=r"(r[3]) : "r"(addr));
}

static __device__ __forceinline__ void ldm4t(uint32_t* r, uint32_t addr) {
    asm volatile("ldmatrix.sync.aligned.m8n8.x4.trans.shared.b16 {%0,%1,%2,%3}, [%4];"
                 : "=r"(r[0]), "=r"(r[1]), "=r"(r[2]), "=r"(r[3]) : "r"(addr));
}

static __device__ __forceinline__ void mma16816(float* c, const uint32_t* a,
                                                const uint32_t* b) {
    asm volatile(
        "mma.sync.aligned.m16n8k16.row.col.f32.f16.f16.f32 "
        "{%0,%1,%2,%3}, {%4,%5,%6,%7}, {%8,%9}, {%0,%1,%2,%3};"
        : "+f"(c[0]), "+f"(c[1]), "+f"(c[2]), "+f"(c[3])
        : "r"(a[0]), "r"(a[1]), "r"(a[2]), "r"(a[3]), "r"(b[0]), "r"(b[1]));
}

static __device__ __forceinline__ float ex2f(float x) {
    float y;
    asm("ex2.approx.ftz.f32 %0, %1;" : "=f"(y) : "f"(x));
    return y;
}

// ---------------- conversion kernels ----------------------------------------
__global__ void conv_x_kernel(const float4* __restrict__ x, uint2* __restrict__ xh, int n4) {
    int i = blockIdx.x * blockDim.x + threadIdx.x;
    if (i < n4) {
        float4 v = x[i];
        __half2 h0 = __floats2half2_rn(v.x, v.y);
        __half2 h1 = __floats2half2_rn(v.z, v.w);
        uint2 u;
        u.x = *reinterpret_cast<uint32_t*>(&h0);
        u.y = *reinterpret_cast<uint32_t*>(&h1);
        xh[i] = u;
    }
}

__global__ void convT_kernel(const float* __restrict__ W, __half* __restrict__ Wt,
                             int R, int C) {
    __shared__ float t[32][33];
    int c0 = blockIdx.x * 32, r0 = blockIdx.y * 32;
    int tx = threadIdx.x, ty = threadIdx.y;
#pragma unroll
    for (int i = 0; i < 4; i++)
        t[ty + i * 8][tx] = W[(size_t)(r0 + ty + i * 8) * C + c0 + tx];
    __syncthreads();
#pragma unroll
    for (int i = 0; i < 4; i++)
        Wt[(size_t)(c0 + ty + i * 8) * R + r0 + tx] = __float2half_rn(t[tx][ty + i * 8]);
}

// ---------------- mma.sync fp16 GEMM -----------------------------------------
// mode 0: scatter fp16 into g_qh/g_kh/g_vh (q pre-scaled).  mode 1: fp32 out.
#define STRIDE_H 40

__global__ __launch_bounds__(256) void gemm_mma(
    const __half* __restrict__ Ah, const __half* __restrict__ Bh,
    const float* __restrict__ bias, float* __restrict__ out,
    int N, int mode) {
    __shared__ __align__(16) __half sA[2][128 * STRIDE_H];
    __shared__ __align__(16) __half sB[2][128 * STRIDE_H];

    const int tid = threadIdx.x;
    const int wid = tid >> 5, lane = tid & 31;
    const int warp_m = wid & 3, warp_n = wid >> 2;
    const int m0 = blockIdx.y * 128, n0 = blockIdx.x * 128;

    const uint32_t sa[2] = { s2u(sA[0]), s2u(sA[1]) };
    const uint32_t sbm[2] = { s2u(sB[0]), s2u(sB[1]) };

    float acc[2][8][4];
#pragma unroll
    for (int mi = 0; mi < 2; mi++)
#pragma unroll
        for (int ni = 0; ni < 8; ni++)
#pragma unroll
            for (int c = 0; c < 4; c++) acc[mi][ni][c] = 0.0f;

    const int r0i = tid >> 2, c0i = tid & 3;
    const int r1i = (tid + 256) >> 2, c1i = tid & 3;

    const int a_row = warp_m * 32 + (lane & 15);
    const int a_kb = (lane >> 4) * 16;
    const int b_row_base = warp_n * 64 + (lane & 7) + ((lane & 16) ? 8 : 0);
    const int b_kb = (lane & 8) ? 16 : 0;

    {
        cpa16(sa[0] + r0i * 80 + c0i * 16, Ah + (size_t)(m0 + r0i) * 1024 + c0i * 8);
        cpa16(sbm[0] + r0i * 80 + c0i * 16, Bh + (size_t)(n0 + r0i) * 1024 + c0i * 8);
        cpa16(sa[0] + r1i * 80 + c1i * 16, Ah + (size_t)(m0 + r1i) * 1024 + c1i * 8);
        cpa16(sbm[0] + r1i * 80 + c1i * 16, Bh + (size_t)(n0 + r1i) * 1024 + c1i * 8);
        asm volatile("cp.async.commit_group;");
    }

#pragma unroll 1
    for (int kc = 0; kc < 32; kc++) {
        const int cur = kc & 1;
        if (kc < 31) {
            const int nb = cur ^ 1;
            const int k0 = (kc + 1) * 32;
            cpa16(sa[nb] + r0i * 80 + c0i * 16, Ah + (size_t)(m0 + r0i) * 1024 + k0 + c0i * 8);
            cpa16(sbm[nb] + r0i * 80 + c0i * 16, Bh + (size_t)(n0 + r0i) * 1024 + k0 + c0i * 8);
            cpa16(sa[nb] + r1i * 80 + c1i * 16, Ah + (size_t)(m0 + r1i) * 1024 + k0 + c1i * 8);
            cpa16(sbm[nb] + r1i * 80 + c1i * 16, Bh + (size_t)(n0 + r1i) * 1024 + k0 + c1i * 8);
            asm volatile("cp.async.commit_group;");
            asm volatile("cp.async.wait_group 1;");
        } else {
            asm volatile("cp.async.wait_group 0;");
        }
        __syncthreads();

#pragma unroll
        for (int ks = 0; ks < 2; ks++) {
            const int kb = ks * 32;
            uint32_t a[2][4];
#pragma unroll
            for (int mi = 0; mi < 2; mi++)
                ldm4(a[mi], sa[cur] + (a_row + mi * 16) * 80 + kb + a_kb);
            uint32_t b[8][2];
#pragma unroll
            for (int ni2 = 0; ni2 < 4; ni2++) {
                uint32_t r[4];
                ldm4(r, sbm[cur] + (b_row_base + ni2 * 16) * 80 + kb + b_kb);
                b[ni2 * 2 + 0][0] = r[0]; b[ni2 * 2 + 0][1] = r[1];
                b[ni2 * 2 + 1][0] = r[2]; b[ni2 * 2 + 1][1] = r[3];
            }
#pragma unroll
            for (int mi = 0; mi < 2; mi++)
#pragma unroll
                for (int ni = 0; ni < 8; ni++)
                    mma16816(acc[mi][ni], a[mi], b[ni]);
        }
        __syncthreads();
    }

    const int rbase = warp_m * 32 + (lane >> 2);
    const int cbase = warp_n * 64 + (lane & 3) * 2;
#pragma unroll
    for (int mi = 0; mi < 2; mi++) {
#pragma unroll
        for (int ni = 0; ni < 8; ni++) {
            const int n = n0 + cbase + ni * 8;
            const float2 bsv = *reinterpret_cast<const float2*>(&bias[n]);
#pragma unroll
            for (int hh = 0; hh < 2; hh++) {
                const int m = m0 + rbase + mi * 16 + hh * 8;
                float vx = acc[mi][ni][hh * 2 + 0] + bsv.x;
                float vy = acc[mi][ni][hh * 2 + 1] + bsv.y;
                if (mode == 0) {
                    const int which = n >> 10;
                    const int ci = n & 1023;
                    const int h = ci >> 6, d = ci & 63;
                    const int b = m >> 11, t = m & 2047;
                    if (which == 0) { vx *= QSCALE; vy *= QSCALE; }
                    __half* dst = (which == 0) ? g_qh : (which == 1) ? g_kh : g_vh;
                    *reinterpret_cast<__half2*>(
                        &dst[(((size_t)b * Hz + h) * Tz + t) * HDz + d]) =
                        __floats2half2_rn(vx, vy);
                } else {
                    float2 v; v.x = vx; v.y = vy;
                    *reinterpret_cast<float2*>(&out[(size_t)m * N + n]) = v;
                }
            }
        }
    }
}

// ---------------- flash attention: mma.sync fp16 ------------------------------
// CTA: 128 q-rows of one (b,h); 4 warps x 32 rows; key tile Bc=64.
// smem (dynamic): Q 128x72h, K 2x64x72h, V 2x64x72h = 55296 B.
#define ATT_SMEM 55296
#define KVSZ 9216   // one 64x72-half buffer in bytes

__global__ __launch_bounds__(128) void attn_mma() {
    extern __shared__ __align__(16) char sm[];
    const uint32_t sQ = s2u(sm);
    const uint32_t sK0 = sQ + 128 * 144;
    const uint32_t sV0 = sK0 + 2 * KVSZ;

    const int tid = threadIdx.x, lane = tid & 31, wid = tid >> 5;
    const int bh = blockIdx.y;
    const int q0 = ((int)gridDim.x - 1 - (int)blockIdx.x) * 128;  // heavy CTAs first

    const __half* qg = g_qh + ((size_t)bh * Tz + q0) * HDz;
    const __half* kg = g_kh + (size_t)bh * Tz * HDz;
    const __half* vg = g_vh + (size_t)bh * Tz * HDz;

    // load Q + prefetch K/V tile 0
    {
#pragma unroll
        for (int i = 0; i < 8; i++) {
            int idx = tid + i * 128, r = idx >> 3, ch = idx & 7;
            cpa16(sQ + r * 144 + ch * 16, qg + r * 64 + ch * 8);
        }
#pragma unroll
        for (int i = 0; i < 4; i++) {
            int idx = tid + i * 128, r = idx >> 3, ch = idx & 7;
            cpa16(sK0 + r * 144 + ch * 16, kg + r * 64 + ch * 8);
            cpa16(sV0 + r * 144 + ch * 16, vg + r * 64 + ch * 8);
        }
        asm volatile("cp.async.commit_group;");
    }

    float accO[2][8][4];
#pragma unroll
    for (int mi = 0; mi < 2; mi++)
#pragma unroll
        for (int ni = 0; ni < 8; ni++)
#pragma unroll
            for (int c = 0; c < 4; c++) accO[mi][ni][c] = 0.0f;
    float mrow[2][2] = { {-1e30f, -1e30f}, {-1e30f, -1e30f} };
    float lrow[2][2] = { {0.0f, 0.0f}, {0.0f, 0.0f} };

    // addr components
    const int qrow_b = wid * 32 + (lane & 15);
    const int q_kb = (lane >> 4) * 16;
    const int k_row = (lane & 7) + ((lane & 16) ? 8 : 0);
    const int k_kb = (lane & 8) ? 16 : 0;
    const int v_row = (lane & 7) + ((lane & 8) ? 8 : 0);
    const int v_cb = (lane & 16) ? 16 : 0;

    const int ntiles = (q0 >> 6) + 2;

#pragma unroll 1
    for (int kt = 0; kt < ntiles; kt++) {
        const int buf = kt & 1;
        if (kt < ntiles - 1) {
            const int nb = buf ^ 1;
            const __half* kgn = kg + (size_t)(kt + 1) * 64 * 64;
            const __half* vgn = vg + (size_t)(kt + 1) * 64 * 64;
#pragma unroll
            for (int i = 0; i < 4; i++) {
                int idx = tid + i * 128, r = idx >> 3, ch = idx & 7;
                cpa16(sK0 + nb * KVSZ + r * 144 + ch * 16, kgn + r * 64 + ch * 8);
                cpa16(sV0 + nb * KVSZ + r * 144 + ch * 16, vgn + r * 64 + ch * 8);
            }
            asm volatile("cp.async.commit_group;");
            asm volatile("cp.async.wait_group 1;");
        } else {
            asm volatile("cp.async.wait_group 0;");
        }
        __syncthreads();

        const uint32_t sk = sK0 + buf * KVSZ;
        const uint32_t sv = sV0 + buf * KVSZ;

        // ---- S = Q @ K^T ----
        float accS[2][8][4];
#pragma unroll
        for (int mi = 0; mi < 2; mi++)
#pragma unroll
            for (int ni = 0; ni < 8; ni++)
#pragma unroll
                for (int c = 0; c < 4; c++) accS[mi][ni][c] = 0.0f;

#pragma unroll
        for (int ks = 0; ks < 4; ks++) {
            uint32_t qa[2][4];
#pragma unroll
            for (int mi = 0; mi < 2; mi++)
                ldm4(qa[mi], sQ + (qrow_b + mi * 16) * 144 + ks * 32 + q_kb);
            uint32_t kb[8][2];
#pragma unroll
            for (int ni2 = 0; ni2 < 4; ni2++) {
                uint32_t r[4];
                ldm4(r, sk + (k_row + ni2 * 16) * 144 + ks * 32 + k_kb);
                kb[ni2 * 2 + 0][0] = r[0]; kb[ni2 * 2 + 0][1] = r[1];
                kb[ni2 * 2 + 1][0] = r[2]; kb[ni2 * 2 + 1][1] = r[3];
            }
#pragma unroll
            for (int mi = 0; mi < 2; mi++)
#pragma unroll
                for (int ni = 0; ni < 8; ni++)
                    mma16816(accS[mi][ni], qa[mi], kb[ni]);
        }

        // ---- causal mask (only last two tiles can straddle the diagonal) ----
        const int k0 = kt * 64;
        if (k0 + 63 > q0) {
            const int row0 = q0 + wid * 32 + (lane >> 2);
            const int colb = k0 + (lane & 3) * 2;
#pragma unroll
            for (int mi = 0; mi < 2; mi++)
#pragma unroll
                for (int ni = 0; ni < 8; ni++) {
                    const int kkb = colb + ni * 8;
                    const int rlo = row0 + mi * 16, rhi = rlo + 8;
                    if (kkb > rlo)     accS[mi][ni][0] = -1e30f;
                    if (kkb + 1 > rlo) accS[mi][ni][1] = -1e30f;
                    if (kkb > rhi)     accS[mi][ni][2] = -1e30f;
                    if (kkb + 1 > rhi) accS[mi][ni][3] = -1e30f;
                }
        }

        // ---- online softmax (base-2; scale folded into Q) ----
#pragma unroll
        for (int mi = 0; mi < 2; mi++) {
            float mx0 = -1e30f, mx1 = -1e30f;
#pragma unroll
            for (int ni = 0; ni < 8; ni++) {
                mx0 = fmaxf(mx0, fmaxf(accS[mi][ni][0], accS[mi][ni][1]));
                mx1 = fmaxf(mx1, fmaxf(accS[mi][ni][2], accS[mi][ni][3]));
            }
            mx0 = fmaxf(mx0, __shfl_xor_sync(0xffffffff, mx0, 1));
            mx0 = fmaxf(mx0, __shfl_xor_sync(0xffffffff, mx0, 2));
            mx1 = fmaxf(mx1, __shfl_xor_sync(0xffffffff, mx1, 1));
            mx1 = fmaxf(mx1, __shfl_xor_sync(0xffffffff, mx1, 2));

            const float mn0 = fmaxf(mrow[mi][0], mx0);
            const float mn1 = fmaxf(mrow[mi][1], mx1);
            const float cor0 = ex2f(mrow[mi][0] - mn0);
            const float cor1 = ex2f(mrow[mi][1] - mn1);
            mrow[mi][0] = mn0; mrow[mi][1] = mn1;

            float sum0 = 0.0f, sum1 = 0.0f;
#pragma unroll
            for (int ni = 0; ni < 8; ni++) {
                float p0 = ex2f(accS[mi][ni][0] - mn0);
                float p1 = ex2f(accS[mi][ni][1] - mn0);
                float p2 = ex2f(accS[mi][ni][2] - mn1);
                float p3 = ex2f(accS[mi][ni][3] - mn1);
                accS[mi][ni][0] = p0; accS[mi][ni][1] = p1;
                accS[mi][ni][2] = p2; accS[mi][ni][3] = p3;
                sum0 += p0 + p1; sum1 += p2 + p3;
                accO[mi][ni][0] *= cor0; accO[mi][ni][1] *= cor0;
                accO[mi][ni][2] *= cor1; accO[mi][ni][3] *= cor1;
            }
            sum0 += __shfl_xor_sync(0xffffffff, sum0, 1);
            sum0 += __shfl_xor_sync(0xffffffff, sum0, 2);
            sum1 += __shfl_xor_sync(0xffffffff, sum1, 1);
            sum1 += __shfl_xor_sync(0xffffffff, sum1, 2);
            lrow[mi][0] = lrow[mi][0] * cor0 + sum0;
            lrow[mi][1] = lrow[mi][1] * cor1 + sum1;
        }

        // ---- O += P @ V ----
#pragma unroll
        for (int ks = 0; ks < 4; ks++) {
            uint32_t vb[8][2];
#pragma unroll
            for (int ni2 = 0; ni2 < 4; ni2++) {
                uint32_t r[4];
                ldm4t(r, sv + (ks * 16 + v_row) * 144 + ni2 * 32 + v_cb);
                vb[ni2 * 2 + 0][0] = r[0]; vb[ni2 * 2 + 0][1] = r[1];
                vb[ni2 * 2 + 1][0] = r[2]; vb[ni2 * 2 + 1][1] = r[3];
            }
#pragma unroll
            for (int mi = 0; mi < 2; mi++) {
                uint32_t pa[4];
                __half2 t0 = __floats2half2_rn(accS[mi][2 * ks][0], accS[mi][2 * ks][1]);
                __half2 t1 = __floats2half2_rn(accS[mi][2 * ks][2], accS[mi][2 * ks][3]);
                __half2 t2 = __floats2half2_rn(accS[mi][2 * ks + 1][0], accS[mi][2 * ks + 1][1]);
                __half2 t3 = __floats2half2_rn(accS[mi][2 * ks + 1][2], accS[mi][2 * ks + 1][3]);
                pa[0] = *reinterpret_cast<uint32_t*>(&t0);
                pa[1] = *reinterpret_cast<uint32_t*>(&t1);
                pa[2] = *reinterpret_cast<uint32_t*>(&t2);
                pa[3] = *reinterpret_cast<uint32_t*>(&t3);
#pragma unroll
                for (int ni = 0; ni < 8; ni++)
                    mma16816(accO[mi][ni], pa, vb[ni]);
            }
        }
        __syncthreads();
    }

    // ---- epilogue: O/l -> g_att_h [B,T,C] fp16 ----
    const int b = bh >> 4, h = bh & 15;
#pragma unroll
    for (int mi = 0; mi < 2; mi++) {
        const float inv0 = 1.0f / lrow[mi][0];
        const float inv1 = 1.0f / lrow[mi][1];
        const int rlo = q0 + wid * 32 + mi * 16 + (lane >> 2);
#pragma unroll
        for (int ni = 0; ni < 8; ni++) {
            const int col = h * HDz + ni * 8 + (lane & 3) * 2;
            *reinterpret_cast<__half2*>(
                &g_att_h[((size_t)b * Tz + rlo) * Cz + col]) =
                __floats2half2_rn(accO[mi][ni][0] * inv0, accO[mi][ni][1] * inv0);
            *reinterpret_cast<__half2*>(
                &g_att_h[((size_t)b * Tz + rlo + 8) * Cz + col]) =
                __floats2half2_rn(accO[mi][ni][2] * inv1, accO[mi][ni][3] * inv1);
        }
    }
}

// ---------------------------------------------------------------------------
extern "C" void kernel_launch(void* const* d_in, const int* in_sizes, int n_in,
                              void* d_out, int out_size) {
    const float* x      = (const float*)d_in[0];
    const float* W_attn = (const float*)d_in[1];
    const float* b_attn = (const float*)d_in[2];
    const float* W_proj = (const float*)d_in[3];
    const float* b_proj = (const float*)d_in[4];
    float* out = (float*)d_out;
    (void)in_sizes; (void)n_in; (void)out_size;

    __half* xh;  cudaGetSymbolAddress((void**)&xh,  g_xh);
    __half* wat; cudaGetSymbolAddress((void**)&wat, g_wat);
    __half* wpt; cudaGetSymbolAddress((void**)&wpt, g_wpt);
    __half* ath; cudaGetSymbolAddress((void**)&ath, g_att_h);

    cudaFuncSetAttribute(attn_mma, cudaFuncAttributeMaxDynamicSharedMemorySize, ATT_SMEM);

    {
        int n4 = Mz * Cz / 4;
        conv_x_kernel<<<(n4 + 255) / 256, 256>>>((const float4*)x, (uint2*)xh, n4);
        dim3 g(3 * Cz / 32, Cz / 32);
        convT_kernel<<<g, dim3(32, 8)>>>(W_attn, wat, Cz, 3 * Cz);
        dim3 g2(Cz / 32, Cz / 32);
        convT_kernel<<<g2, dim3(32, 8)>>>(W_proj, wpt, Cz, Cz);
    }

    // QKV GEMM: M=8192, N=3072 -> fp16 q/k/v
    dim3 g1(3 * Cz / 128, Mz / 128);
    gemm_mma<<<g1, 256>>>(xh, wat, b_attn, nullptr, 3 * Cz, 0);

    // Flash attention (mma.sync)
    dim3 g2(Tz / 128, Bz * Hz);
    attn_mma<<<g2, 128, ATT_SMEM>>>();

    // Projection: M=8192, N=1024
    dim3 g3(Cz / 128, Mz / 128);
    gemm_mma<<<g3, 256>>>(ath, wpt, b_proj, out, Cz, 1);
}

// round 5
// speedup vs baseline: 7.8886x; 1.0401x over previous
#include <cuda_runtime.h>
#include <cuda_fp16.h>
#include <math.h>
#include <stdint.h>

#define Bz 4
#define Tz 2048
#define Cz 1024
#define Hz 16
#define HDz 64
#define Mz (Bz * Tz)

#define QSCALE 0.1803368801111204f   // 1/sqrt(64) * log2(e)

// ---------------- scratch ----------------------------------------------------
__device__ __half g_qh[(size_t)Bz * Hz * Tz * HDz];
__device__ __half g_kh[(size_t)Bz * Hz * Tz * HDz];
__device__ __half g_vh[(size_t)Bz * Hz * Tz * HDz];
__device__ __half g_xh[(size_t)Mz * Cz];
__device__ __half g_wat[(size_t)3 * Cz * Cz];
__device__ __half g_wpt[(size_t)Cz * Cz];
__device__ __half g_att_h[(size_t)Mz * Cz];

// ---------------- helpers ----------------------------------------------------
static __device__ __forceinline__ uint32_t s2u(const void* p) {
    uint32_t a;
    asm("{ .reg .u64 t; cvta.to.shared.u64 t, %1; cvt.u32.u64 %0, t; }"
        : "=r"(a) : "l"(p));
    return a;
}

static __device__ __forceinline__ void cpa16(uint32_t dst, const void* src) {
    asm volatile("cp.async.cg.shared.global [%0], [%1], 16;"
                 :: "r"(dst), "l"(__cvta_generic_to_global(src)));
}

static __device__ __forceinline__ void ldm4(uint32_t* r, uint32_t addr) {
    asm volatile("ldmatrix.sync.aligned.m8n8.x4.shared.b16 {%0,%1,%2,%3}, [%4];"
                 : "=r"(r[0]), "=r"(r[1]), "=r"(r[2]), "=r"(r[3]) : "r"(addr));
}

static __device__ __forceinline__ void ldm4t(uint32_t* r, uint32_t addr) {
    asm volatile("ldmatrix.sync.aligned.m8n8.x4.trans.shared.b16 {%0,%1,%2,%3}, [%4];"
                 : "=r"(r[0]), "=r"(r[1]), "=r"(r[2]), "=r"(r[3]) : "r"(addr));
}

static __device__ __forceinline__ void mma16816(float* c, const uint32_t* a,
                                                const uint32_t* b) {
    asm volatile(
        "mma.sync.aligned.m16n8k16.row.col.f32.f16.f16.f32 "
        "{%0,%1,%2,%3}, {%4,%5,%6,%7}, {%8,%9}, {%0,%1,%2,%3};"
        : "+f"(c[0]), "+f"(c[1]), "+f"(c[2]), "+f"(c[3])
        : "r"(a[0]), "r"(a[1]), "r"(a[2]), "r"(a[3]), "r"(b[0]), "r"(b[1]));
}

static __device__ __forceinline__ float ex2f(float x) {
    float y;
    asm("ex2.approx.ftz.f32 %0, %1;" : "=f"(y) : "f"(x));
    return y;
}

// ---------------- conversion kernels ----------------------------------------
__global__ void conv_x_kernel(const float4* __restrict__ x, uint2* __restrict__ xh, int n4) {
    int i = blockIdx.x * blockDim.x + threadIdx.x;
    if (i < n4) {
        float4 v = x[i];
        __half2 h0 = __floats2half2_rn(v.x, v.y);
        __half2 h1 = __floats2half2_rn(v.z, v.w);
        uint2 u;
        u.x = *reinterpret_cast<uint32_t*>(&h0);
        u.y = *reinterpret_cast<uint32_t*>(&h1);
        xh[i] = u;
    }
}

__global__ void convT_kernel(const float* __restrict__ W, __half* __restrict__ Wt,
                             int R, int C) {
    __shared__ float t[32][33];
    int c0 = blockIdx.x * 32, r0 = blockIdx.y * 32;
    int tx = threadIdx.x, ty = threadIdx.y;
#pragma unroll
    for (int i = 0; i < 4; i++)
        t[ty + i * 8][tx] = W[(size_t)(r0 + ty + i * 8) * C + c0 + tx];
    __syncthreads();
#pragma unroll
    for (int i = 0; i < 4; i++)
        Wt[(size_t)(c0 + ty + i * 8) * R + r0 + tx] = __float2half_rn(t[tx][ty + i * 8]);
}

// ---------------- mma.sync fp16 GEMM, 4-stage pipeline ------------------------
// D[128,128] = A[M,1024] @ B[N,1024]^T.  chunk=32, NSTAGE=4, ONE sync/iter.
#define NSTAGE 4
#define STG_B 10240            // one 128x40-half tile in bytes
#define GEMM_SMEM (NSTAGE * STG_B * 2)

__global__ __launch_bounds__(256) void gemm_mma(
    const __half* __restrict__ Ah, const __half* __restrict__ Bh,
    const float* __restrict__ bias, float* __restrict__ out,
    int N, int mode) {
    extern __shared__ __align__(16) char gsm[];
    const uint32_t sa_base = s2u(gsm);
    const uint32_t sb_base = sa_base + NSTAGE * STG_B;

    const int tid = threadIdx.x;
    const int wid = tid >> 5, lane = tid & 31;
    const int warp_m = wid & 3, warp_n = wid >> 2;
    const int m0 = blockIdx.y * 128, n0 = blockIdx.x * 128;

    float acc[2][8][4];
#pragma unroll
    for (int mi = 0; mi < 2; mi++)
#pragma unroll
        for (int ni = 0; ni < 8; ni++)
#pragma unroll
            for (int c = 0; c < 4; c++) acc[mi][ni][c] = 0.0f;

    const int r0i = tid >> 2, c0i = tid & 3;
    const int r1i = (tid + 256) >> 2;

    const int a_row = warp_m * 32 + (lane & 15);
    const int a_kb = (lane >> 4) * 16;
    const int b_row_base = warp_n * 64 + (lane & 7) + ((lane & 16) ? 8 : 0);
    const int b_kb = (lane & 8) ? 16 : 0;

    const __half* arow0 = Ah + (size_t)(m0 + r0i) * 1024 + c0i * 8;
    const __half* arow1 = Ah + (size_t)(m0 + r1i) * 1024 + c0i * 8;
    const __half* brow0 = Bh + (size_t)(n0 + r0i) * 1024 + c0i * 8;
    const __half* brow1 = Bh + (size_t)(n0 + r1i) * 1024 + c0i * 8;
    const uint32_t soff0 = r0i * 80 + c0i * 16;
    const uint32_t soff1 = r1i * 80 + c0i * 16;

    // prologue: stages 0..2
#pragma unroll
    for (int s = 0; s < NSTAGE - 1; s++) {
        const int k0 = s * 32;
        cpa16(sa_base + s * STG_B + soff0, arow0 + k0);
        cpa16(sa_base + s * STG_B + soff1, arow1 + k0);
        cpa16(sb_base + s * STG_B + soff0, brow0 + k0);
        cpa16(sb_base + s * STG_B + soff1, brow1 + k0);
        asm volatile("cp.async.commit_group;");
    }

#pragma unroll 1
    for (int kc = 0; kc < 32; kc++) {
        asm volatile("cp.async.wait_group %0;" :: "n"(NSTAGE - 2));
        __syncthreads();

        // issue stage kc+3 (or an empty group to keep wait arithmetic exact)
        if (kc + NSTAGE - 1 < 32) {
            const int s = (kc + NSTAGE - 1) & (NSTAGE - 1);
            const int k0 = (kc + NSTAGE - 1) * 32;
            cpa16(sa_base + s * STG_B + soff0, arow0 + k0);
            cpa16(sa_base + s * STG_B + soff1, arow1 + k0);
            cpa16(sb_base + s * STG_B + soff0, brow0 + k0);
            cpa16(sb_base + s * STG_B + soff1, brow1 + k0);
        }
        asm volatile("cp.async.commit_group;");

        const uint32_t sa = sa_base + (kc & (NSTAGE - 1)) * STG_B;
        const uint32_t sb = sb_base + (kc & (NSTAGE - 1)) * STG_B;
#pragma unroll
        for (int ks = 0; ks < 2; ks++) {
            const int kb = ks * 32;
            uint32_t a[2][4];
#pragma unroll
            for (int mi = 0; mi < 2; mi++)
                ldm4(a[mi], sa + (a_row + mi * 16) * 80 + kb + a_kb);
            uint32_t b[8][2];
#pragma unroll
            for (int ni2 = 0; ni2 < 4; ni2++) {
                uint32_t r[4];
                ldm4(r, sb + (b_row_base + ni2 * 16) * 80 + kb + b_kb);
                b[ni2 * 2 + 0][0] = r[0]; b[ni2 * 2 + 0][1] = r[1];
                b[ni2 * 2 + 1][0] = r[2]; b[ni2 * 2 + 1][1] = r[3];
            }
#pragma unroll
            for (int mi = 0; mi < 2; mi++)
#pragma unroll
                for (int ni = 0; ni < 8; ni++)
                    mma16816(acc[mi][ni], a[mi], b[ni]);
        }
    }

    const int rbase = warp_m * 32 + (lane >> 2);
    const int cbase = warp_n * 64 + (lane & 3) * 2;
#pragma unroll
    for (int mi = 0; mi < 2; mi++) {
#pragma unroll
        for (int ni = 0; ni < 8; ni++) {
            const int n = n0 + cbase + ni * 8;
            const float2 bsv = *reinterpret_cast<const float2*>(&bias[n]);
#pragma unroll
            for (int hh = 0; hh < 2; hh++) {
                const int m = m0 + rbase + mi * 16 + hh * 8;
                float vx = acc[mi][ni][hh * 2 + 0] + bsv.x;
                float vy = acc[mi][ni][hh * 2 + 1] + bsv.y;
                if (mode == 0) {
                    const int which = n >> 10;
                    const int ci = n & 1023;
                    const int h = ci >> 6, d = ci & 63;
                    const int b = m >> 11, t = m & 2047;
                    if (which == 0) { vx *= QSCALE; vy *= QSCALE; }
                    __half* dst = (which == 0) ? g_qh : (which == 1) ? g_kh : g_vh;
                    *reinterpret_cast<__half2*>(
                        &dst[(((size_t)b * Hz + h) * Tz + t) * HDz + d]) =
                        __floats2half2_rn(vx, vy);
                } else {
                    float2 v; v.x = vx; v.y = vy;
                    *reinterpret_cast<float2*>(&out[(size_t)m * N + n]) = v;
                }
            }
        }
    }
}

// ---------------- flash attention: mma.sync fp16 ------------------------------
#define ATT_SMEM 55296
#define KVSZ 9216

__global__ __launch_bounds__(128) void attn_mma() {
    extern __shared__ __align__(16) char sm[];
    const uint32_t sQ = s2u(sm);
    const uint32_t sK0 = sQ + 128 * 144;
    const uint32_t sV0 = sK0 + 2 * KVSZ;

    const int tid = threadIdx.x, lane = tid & 31, wid = tid >> 5;
    const int bh = blockIdx.y;
    const int q0 = ((int)gridDim.x - 1 - (int)blockIdx.x) * 128;

    const __half* qg = g_qh + ((size_t)bh * Tz + q0) * HDz;
    const __half* kg = g_kh + (size_t)bh * Tz * HDz;
    const __half* vg = g_vh + (size_t)bh * Tz * HDz;

    {
#pragma unroll
        for (int i = 0; i < 8; i++) {
            int idx = tid + i * 128, r = idx >> 3, ch = idx & 7;
            cpa16(sQ + r * 144 + ch * 16, qg + r * 64 + ch * 8);
        }
#pragma unroll
        for (int i = 0; i < 4; i++) {
            int idx = tid + i * 128, r = idx >> 3, ch = idx & 7;
            cpa16(sK0 + r * 144 + ch * 16, kg + r * 64 + ch * 8);
            cpa16(sV0 + r * 144 + ch * 16, vg + r * 64 + ch * 8);
        }
        asm volatile("cp.async.commit_group;");
    }

    float accO[2][8][4];
#pragma unroll
    for (int mi = 0; mi < 2; mi++)
#pragma unroll
        for (int ni = 0; ni < 8; ni++)
#pragma unroll
            for (int c = 0; c < 4; c++) accO[mi][ni][c] = 0.0f;
    float mrow[2][2] = { {-1e30f, -1e30f}, {-1e30f, -1e30f} };
    float lrow[2][2] = { {0.0f, 0.0f}, {0.0f, 0.0f} };

    const int qrow_b = wid * 32 + (lane & 15);
    const int q_kb = (lane >> 4) * 16;
    const int k_row = (lane & 7) + ((lane & 16) ? 8 : 0);
    const int k_kb = (lane & 8) ? 16 : 0;
    const int v_row = (lane & 7) + ((lane & 8) ? 8 : 0);
    const int v_cb = (lane & 16) ? 16 : 0;

    const int ntiles = (q0 >> 6) + 2;

#pragma unroll 1
    for (int kt = 0; kt < ntiles; kt++) {
        const int buf = kt & 1;
        if (kt < ntiles - 1) {
            const int nb = buf ^ 1;
            const __half* kgn = kg + (size_t)(kt + 1) * 64 * 64;
            const __half* vgn = vg + (size_t)(kt + 1) * 64 * 64;
#pragma unroll
            for (int i = 0; i < 4; i++) {
                int idx = tid + i * 128, r = idx >> 3, ch = idx & 7;
                cpa16(sK0 + nb * KVSZ + r * 144 + ch * 16, kgn + r * 64 + ch * 8);
                cpa16(sV0 + nb * KVSZ + r * 144 + ch * 16, vgn + r * 64 + ch * 8);
            }
            asm volatile("cp.async.commit_group;");
            asm volatile("cp.async.wait_group 1;");
        } else {
            asm volatile("cp.async.wait_group 0;");
        }
        __syncthreads();

        const uint32_t sk = sK0 + buf * KVSZ;
        const uint32_t sv = sV0 + buf * KVSZ;

        float accS[2][8][4];
#pragma unroll
        for (int mi = 0; mi < 2; mi++)
#pragma unroll
            for (int ni = 0; ni < 8; ni++)
#pragma unroll
                for (int c = 0; c < 4; c++) accS[mi][ni][c] = 0.0f;

#pragma unroll
        for (int ks = 0; ks < 4; ks++) {
            uint32_t qa[2][4];
#pragma unroll
            for (int mi = 0; mi < 2; mi++)
                ldm4(qa[mi], sQ + (qrow_b + mi * 16) * 144 + ks * 32 + q_kb);
            uint32_t kb[8][2];
#pragma unroll
            for (int ni2 = 0; ni2 < 4; ni2++) {
                uint32_t r[4];
                ldm4(r, sk + (k_row + ni2 * 16) * 144 + ks * 32 + k_kb);
                kb[ni2 * 2 + 0][0] = r[0]; kb[ni2 * 2 + 0][1] = r[1];
                kb[ni2 * 2 + 1][0] = r[2]; kb[ni2 * 2 + 1][1] = r[3];
            }
#pragma unroll
            for (int mi = 0; mi < 2; mi++)
#pragma unroll
                for (int ni = 0; ni < 8; ni++)
                    mma16816(accS[mi][ni], qa[mi], kb[ni]);
        }

        const int k0 = kt * 64;
        if (k0 + 63 > q0) {
            const int row0 = q0 + wid * 32 + (lane >> 2);
            const int colb = k0 + (lane & 3) * 2;
#pragma unroll
            for (int mi = 0; mi < 2; mi++)
#pragma unroll
                for (int ni = 0; ni < 8; ni++) {
                    const int kkb = colb + ni * 8;
                    const int rlo = row0 + mi * 16, rhi = rlo + 8;
                    if (kkb > rlo)     accS[mi][ni][0] = -1e30f;
                    if (kkb + 1 > rlo) accS[mi][ni][1] = -1e30f;
                    if (kkb > rhi)     accS[mi][ni][2] = -1e30f;
                    if (kkb + 1 > rhi) accS[mi][ni][3] = -1e30f;
                }
        }

#pragma unroll
        for (int mi = 0; mi < 2; mi++) {
            float mx0 = -1e30f, mx1 = -1e30f;
#pragma unroll
            for (int ni = 0; ni < 8; ni++) {
                mx0 = fmaxf(mx0, fmaxf(accS[mi][ni][0], accS[mi][ni][1]));
                mx1 = fmaxf(mx1, fmaxf(accS[mi][ni][2], accS[mi][ni][3]));
            }
            mx0 = fmaxf(mx0, __shfl_xor_sync(0xffffffff, mx0, 1));
            mx0 = fmaxf(mx0, __shfl_xor_sync(0xffffffff, mx0, 2));
            mx1 = fmaxf(mx1, __shfl_xor_sync(0xffffffff, mx1, 1));
            mx1 = fmaxf(mx1, __shfl_xor_sync(0xffffffff, mx1, 2));

            const float mn0 = fmaxf(mrow[mi][0], mx0);
            const float mn1 = fmaxf(mrow[mi][1], mx1);
            const float cor0 = ex2f(mrow[mi][0] - mn0);
            const float cor1 = ex2f(mrow[mi][1] - mn1);
            mrow[mi][0] = mn0; mrow[mi][1] = mn1;

            float sum0 = 0.0f, sum1 = 0.0f;
#pragma unroll
            for (int ni = 0; ni < 8; ni++) {
                float p0 = ex2f(accS[mi][ni][0] - mn0);
                float p1 = ex2f(accS[mi][ni][1] - mn0);
                float p2 = ex2f(accS[mi][ni][2] - mn1);
                float p3 = ex2f(accS[mi][ni][3] - mn1);
                accS[mi][ni][0] = p0; accS[mi][ni][1] = p1;
                accS[mi][ni][2] = p2; accS[mi][ni][3] = p3;
                sum0 += p0 + p1; sum1 += p2 + p3;
                accO[mi][ni][0] *= cor0; accO[mi][ni][1] *= cor0;
                accO[mi][ni][2] *= cor1; accO[mi][ni][3] *= cor1;
            }
            sum0 += __shfl_xor_sync(0xffffffff, sum0, 1);
            sum0 += __shfl_xor_sync(0xffffffff, sum0, 2);
            sum1 += __shfl_xor_sync(0xffffffff, sum1, 1);
            sum1 += __shfl_xor_sync(0xffffffff, sum1, 2);
            lrow[mi][0] = lrow[mi][0] * cor0 + sum0;
            lrow[mi][1] = lrow[mi][1] * cor1 + sum1;
        }

#pragma unroll
        for (int ks = 0; ks < 4; ks++) {
            uint32_t vb[8][2];
#pragma unroll
            for (int ni2 = 0; ni2 < 4; ni2++) {
                uint32_t r[4];
                ldm4t(r, sv + (ks * 16 + v_row) * 144 + ni2 * 32 + v_cb);
                vb[ni2 * 2 + 0][0] = r[0]; vb[ni2 * 2 + 0][1] = r[1];
                vb[ni2 * 2 + 1][0] = r[2]; vb[ni2 * 2 + 1][1] = r[3];
            }
#pragma unroll
            for (int mi = 0; mi < 2; mi++) {
                uint32_t pa[4];
                __half2 t0 = __floats2half2_rn(accS[mi][2 * ks][0], accS[mi][2 * ks][1]);
                __half2 t1 = __floats2half2_rn(accS[mi][2 * ks][2], accS[mi][2 * ks][3]);
                __half2 t2 = __floats2half2_rn(accS[mi][2 * ks + 1][0], accS[mi][2 * ks + 1][1]);
                __half2 t3 = __floats2half2_rn(accS[mi][2 * ks + 1][2], accS[mi][2 * ks + 1][3]);
                pa[0] = *reinterpret_cast<uint32_t*>(&t0);
                pa[1] = *reinterpret_cast<uint32_t*>(&t1);
                pa[2] = *reinterpret_cast<uint32_t*>(&t2);
                pa[3] = *reinterpret_cast<uint32_t*>(&t3);
#pragma unroll
                for (int ni = 0; ni < 8; ni++)
                    mma16816(accO[mi][ni], pa, vb[ni]);
            }
        }
        __syncthreads();
    }

    const int b = bh >> 4, h = bh & 15;
#pragma unroll
    for (int mi = 0; mi < 2; mi++) {
        const float inv0 = 1.0f / lrow[mi][0];
        const float inv1 = 1.0f / lrow[mi][1];
        const int rlo = q0 + wid * 32 + mi * 16 + (lane >> 2);
#pragma unroll
        for (int ni = 0; ni < 8; ni++) {
            const int col = h * HDz + ni * 8 + (lane & 3) * 2;
            *reinterpret_cast<__half2*>(
                &g_att_h[((size_t)b * Tz + rlo) * Cz + col]) =
                __floats2half2_rn(accO[mi][ni][0] * inv0, accO[mi][ni][1] * inv0);
            *reinterpret_cast<__half2*>(
                &g_att_h[((size_t)b * Tz + rlo + 8) * Cz + col]) =
                __floats2half2_rn(accO[mi][ni][2] * inv1, accO[mi][ni][3] * inv1);
        }
    }
}

// ---------------------------------------------------------------------------
extern "C" void kernel_launch(void* const* d_in, const int* in_sizes, int n_in,
                              void* d_out, int out_size) {
    const float* x      = (const float*)d_in[0];
    const float* W_attn = (const float*)d_in[1];
    const float* b_attn = (const float*)d_in[2];
    const float* W_proj = (const float*)d_in[3];
    const float* b_proj = (const float*)d_in[4];
    float* out = (float*)d_out;
    (void)in_sizes; (void)n_in; (void)out_size;

    __half* xh;  cudaGetSymbolAddress((void**)&xh,  g_xh);
    __half* wat; cudaGetSymbolAddress((void**)&wat, g_wat);
    __half* wpt; cudaGetSymbolAddress((void**)&wpt, g_wpt);
    __half* ath; cudaGetSymbolAddress((void**)&ath, g_att_h);

    cudaFuncSetAttribute(gemm_mma, cudaFuncAttributeMaxDynamicSharedMemorySize, GEMM_SMEM);
    cudaFuncSetAttribute(attn_mma, cudaFuncAttributeMaxDynamicSharedMemorySize, ATT_SMEM);

    {
        int n4 = Mz * Cz / 4;
        conv_x_kernel<<<(n4 + 255) / 256, 256>>>((const float4*)x, (uint2*)xh, n4);
        dim3 g(3 * Cz / 32, Cz / 32);
        convT_kernel<<<g, dim3(32, 8)>>>(W_attn, wat, Cz, 3 * Cz);
        dim3 g2(Cz / 32, Cz / 32);
        convT_kernel<<<g2, dim3(32, 8)>>>(W_proj, wpt, Cz, Cz);
    }

    dim3 g1(3 * Cz / 128, Mz / 128);
    gemm_mma<<<g1, 256, GEMM_SMEM>>>(xh, wat, b_attn, nullptr, 3 * Cz, 0);

    dim3 g2(Tz / 128, Bz * Hz);
    attn_mma<<<g2, 128, ATT_SMEM>>>();

    dim3 g3(Cz / 128, Mz / 128);
    gemm_mma<<<g3, 256, GEMM_SMEM>>>(ath, wpt, b_proj, out, Cz, 1);
}

// round 6
// speedup vs baseline: 8.8752x; 1.1251x over previous
#include <cuda_runtime.h>
#include <cuda_fp16.h>
#include <math.h>
#include <stdint.h>

#define Bz 4
#define Tz 2048
#define Cz 1024
#define Hz 16
#define HDz 64
#define Mz (Bz * Tz)

#define QSCALE 0.1803368801111204f   // 1/sqrt(64) * log2(e)

// ---------------- scratch ----------------------------------------------------
__device__ __half g_qh[(size_t)Bz * Hz * Tz * HDz];
__device__ __half g_kh[(size_t)Bz * Hz * Tz * HDz];
__device__ __half g_vh[(size_t)Bz * Hz * Tz * HDz];
__device__ __half g_xh[(size_t)Mz * Cz];
__device__ __half g_wat[(size_t)3 * Cz * Cz];
__device__ __half g_wpt[(size_t)Cz * Cz];
__device__ __half g_att_h[(size_t)Mz * Cz];

// ---------------- helpers ----------------------------------------------------
static __device__ __forceinline__ uint32_t s2u(const void* p) {
    uint32_t a;
    asm("{ .reg .u64 t; cvta.to.shared.u64 t, %1; cvt.u32.u64 %0, t; }"
        : "=r"(a) : "l"(p));
    return a;
}

static __device__ __forceinline__ void cpa16(uint32_t dst, const void* src) {
    asm volatile("cp.async.cg.shared.global [%0], [%1], 16;"
                 :: "r"(dst), "l"(__cvta_generic_to_global(src)));
}

static __device__ __forceinline__ void ldm4(uint32_t* r, uint32_t addr) {
    asm volatile("ldmatrix.sync.aligned.m8n8.x4.shared.b16 {%0,%1,%2,%3}, [%4];"
                 : "=r"(r[0]), "=r"(r[1]), "=r"(r[2]), "=r"(r[3]) : "r"(addr));
}

static __device__ __forceinline__ void ldm4t(uint32_t* r, uint32_t addr) {
    asm volatile("ldmatrix.sync.aligned.m8n8.x4.trans.shared.b16 {%0,%1,%2,%3}, [%4];"
                 : "=r"(r[0]), "=r"(r[1]), "=r"(r[2]), "=r"(r[3]) : "r"(addr));
}

static __device__ __forceinline__ void mma16816(float* c, const uint32_t* a,
                                                const uint32_t* b) {
    asm volatile(
        "mma.sync.aligned.m16n8k16.row.col.f32.f16.f16.f32 "
        "{%0,%1,%2,%3}, {%4,%5,%6,%7}, {%8,%9}, {%0,%1,%2,%3};"
        : "+f"(c[0]), "+f"(c[1]), "+f"(c[2]), "+f"(c[3])
        : "r"(a[0]), "r"(a[1]), "r"(a[2]), "r"(a[3]), "r"(b[0]), "r"(b[1]));
}

static __device__ __forceinline__ float ex2f(float x) {
    float y;
    asm("ex2.approx.ftz.f32 %0, %1;" : "=f"(y) : "f"(x));
    return y;
}

// ---------------- conversion kernels ----------------------------------------
__global__ void conv_x_kernel(const float4* __restrict__ x, uint2* __restrict__ xh, int n4) {
    int i = blockIdx.x * blockDim.x + threadIdx.x;
    if (i < n4) {
        float4 v = x[i];
        __half2 h0 = __floats2half2_rn(v.x, v.y);
        __half2 h1 = __floats2half2_rn(v.z, v.w);
        uint2 u;
        u.x = *reinterpret_cast<uint32_t*>(&h0);
        u.y = *reinterpret_cast<uint32_t*>(&h1);
        xh[i] = u;
    }
}

__global__ void convT_kernel(const float* __restrict__ W, __half* __restrict__ Wt,
                             int R, int C) {
    __shared__ float t[32][33];
    int c0 = blockIdx.x * 32, r0 = blockIdx.y * 32;
    int tx = threadIdx.x, ty = threadIdx.y;
#pragma unroll
    for (int i = 0; i < 4; i++)
        t[ty + i * 8][tx] = W[(size_t)(r0 + ty + i * 8) * C + c0 + tx];
    __syncthreads();
#pragma unroll
    for (int i = 0; i < 4; i++)
        Wt[(size_t)(c0 + ty + i * 8) * R + r0 + tx] = __float2half_rn(t[tx][ty + i * 8]);
}

// ---------------- mma.sync fp16 GEMM: 4 warps, 64x64 warp tiles ---------------
// D[128,128] = A[M,1024] @ B[N,1024]^T.  chunk=32, NSTAGE=4, 128 threads.
#define NSTAGE 4
#define STG_B 20480            // A (128x40h=10240B) + B (10240B) per stage
#define GEMM_SMEM (NSTAGE * STG_B)

__global__ __launch_bounds__(128, 2) void gemm_mma(
    const __half* __restrict__ Ah, const __half* __restrict__ Bh,
    const float* __restrict__ bias, float* __restrict__ out,
    int N, int mode) {
    extern __shared__ __align__(16) char gsm[];
    const uint32_t s_base = s2u(gsm);

    const int tid = threadIdx.x;
    const int wid = tid >> 5, lane = tid & 31;
    const int warp_m = wid & 1, warp_n = wid >> 1;     // 2x2 warps of 64x64
    const int m0 = blockIdx.y * 128, n0 = blockIdx.x * 128;

    float acc[4][8][4];
#pragma unroll
    for (int mi = 0; mi < 4; mi++)
#pragma unroll
        for (int ni = 0; ni < 8; ni++)
#pragma unroll
            for (int c = 0; c < 4; c++) acc[mi][ni][c] = 0.0f;

    // loader indices: 512 16B-chunks per operand tile, 4 per thread
    const int lrow = tid >> 2;          // rows tid>>2, +32, +64, +96
    const int lcol = (tid & 3) * 16;    // byte col within 64B row data
    const int gcol = (tid & 3) * 8;     // halves

    const int a_row = warp_m * 64 + (lane & 15);
    const int a_kb = (lane >> 4) * 16;
    const int b_row_base = warp_n * 64 + (lane & 7) + ((lane & 16) ? 8 : 0);
    const int b_kb = (lane & 8) ? 16 : 0;

    // prologue: stages 0..2
#pragma unroll
    for (int s = 0; s < NSTAGE - 1; s++) {
        const int k0 = s * 32;
        const uint32_t sa = s_base + s * STG_B;
#pragma unroll
        for (int i = 0; i < 4; i++) {
            const int r = lrow + i * 32;
            cpa16(sa + r * 80 + lcol, Ah + (size_t)(m0 + r) * 1024 + k0 + gcol);
            cpa16(sa + 10240 + r * 80 + lcol, Bh + (size_t)(n0 + r) * 1024 + k0 + gcol);
        }
        asm volatile("cp.async.commit_group;");
    }

#pragma unroll 1
    for (int kc = 0; kc < 32; kc++) {
        asm volatile("cp.async.wait_group %0;" :: "n"(NSTAGE - 2));
        __syncthreads();

        if (kc + NSTAGE - 1 < 32) {
            const int s = (kc + NSTAGE - 1) & (NSTAGE - 1);
            const int k0 = (kc + NSTAGE - 1) * 32;
            const uint32_t sa = s_base + s * STG_B;
#pragma unroll
            for (int i = 0; i < 4; i++) {
                const int r = lrow + i * 32;
                cpa16(sa + r * 80 + lcol, Ah + (size_t)(m0 + r) * 1024 + k0 + gcol);
                cpa16(sa + 10240 + r * 80 + lcol, Bh + (size_t)(n0 + r) * 1024 + k0 + gcol);
            }
        }
        asm volatile("cp.async.commit_group;");

        const uint32_t sa = s_base + (kc & (NSTAGE - 1)) * STG_B;
        const uint32_t sb = sa + 10240;
#pragma unroll
        for (int ks = 0; ks < 2; ks++) {
            const int kb = ks * 32;
            uint32_t a[4][4];
#pragma unroll
            for (int mi = 0; mi < 4; mi++)
                ldm4(a[mi], sa + (a_row + mi * 16) * 80 + kb + a_kb);
            uint32_t b[8][2];
#pragma unroll
            for (int ni2 = 0; ni2 < 4; ni2++) {
                uint32_t r[4];
                ldm4(r, sb + (b_row_base + ni2 * 16) * 80 + kb + b_kb);
                b[ni2 * 2 + 0][0] = r[0]; b[ni2 * 2 + 0][1] = r[1];
                b[ni2 * 2 + 1][0] = r[2]; b[ni2 * 2 + 1][1] = r[3];
            }
#pragma unroll
            for (int mi = 0; mi < 4; mi++)
#pragma unroll
                for (int ni = 0; ni < 8; ni++)
                    mma16816(acc[mi][ni], a[mi], b[ni]);
        }
    }

    const int rbase = warp_m * 64 + (lane >> 2);
    const int cbase = warp_n * 64 + (lane & 3) * 2;
#pragma unroll
    for (int mi = 0; mi < 4; mi++) {
#pragma unroll
        for (int ni = 0; ni < 8; ni++) {
            const int n = n0 + cbase + ni * 8;
            const float2 bsv = *reinterpret_cast<const float2*>(&bias[n]);
#pragma unroll
            for (int hh = 0; hh < 2; hh++) {
                const int m = m0 + rbase + mi * 16 + hh * 8;
                float vx = acc[mi][ni][hh * 2 + 0] + bsv.x;
                float vy = acc[mi][ni][hh * 2 + 1] + bsv.y;
                if (mode == 0) {
                    const int which = n >> 10;
                    const int ci = n & 1023;
                    const int h = ci >> 6, d = ci & 63;
                    const int b = m >> 11, t = m & 2047;
                    if (which == 0) { vx *= QSCALE; vy *= QSCALE; }
                    __half* dst = (which == 0) ? g_qh : (which == 1) ? g_kh : g_vh;
                    *reinterpret_cast<__half2*>(
                        &dst[(((size_t)b * Hz + h) * Tz + t) * HDz + d]) =
                        __floats2half2_rn(vx, vy);
                } else {
                    float2 v; v.x = vx; v.y = vy;
                    *reinterpret_cast<float2*>(&out[(size_t)m * N + n]) = v;
                }
            }
        }
    }
}

// ---------------- flash attention: mma.sync fp16 ------------------------------
#define ATT_SMEM 55296
#define KVSZ 9216

__global__ __launch_bounds__(128) void attn_mma() {
    extern __shared__ __align__(16) char sm[];
    const uint32_t sQ = s2u(sm);
    const uint32_t sK0 = sQ + 128 * 144;
    const uint32_t sV0 = sK0 + 2 * KVSZ;

    const int tid = threadIdx.x, lane = tid & 31, wid = tid >> 5;
    const int bh = blockIdx.y;
    const int q0 = ((int)gridDim.x - 1 - (int)blockIdx.x) * 128;

    const __half* qg = g_qh + ((size_t)bh * Tz + q0) * HDz;
    const __half* kg = g_kh + (size_t)bh * Tz * HDz;
    const __half* vg = g_vh + (size_t)bh * Tz * HDz;

    {
#pragma unroll
        for (int i = 0; i < 8; i++) {
            int idx = tid + i * 128, r = idx >> 3, ch = idx & 7;
            cpa16(sQ + r * 144 + ch * 16, qg + r * 64 + ch * 8);
        }
#pragma unroll
        for (int i = 0; i < 4; i++) {
            int idx = tid + i * 128, r = idx >> 3, ch = idx & 7;
            cpa16(sK0 + r * 144 + ch * 16, kg + r * 64 + ch * 8);
            cpa16(sV0 + r * 144 + ch * 16, vg + r * 64 + ch * 8);
        }
        asm volatile("cp.async.commit_group;");
    }

    float accO[2][8][4];
#pragma unroll
    for (int mi = 0; mi < 2; mi++)
#pragma unroll
        for (int ni = 0; ni < 8; ni++)
#pragma unroll
            for (int c = 0; c < 4; c++) accO[mi][ni][c] = 0.0f;
    float mrow[2][2] = { {-1e30f, -1e30f}, {-1e30f, -1e30f} };
    float lrow[2][2] = { {0.0f, 0.0f}, {0.0f, 0.0f} };

    const int qrow_b = wid * 32 + (lane & 15);
    const int q_kb = (lane >> 4) * 16;
    const int k_row = (lane & 7) + ((lane & 16) ? 8 : 0);
    const int k_kb = (lane & 8) ? 16 : 0;
    const int v_row = (lane & 7) + ((lane & 8) ? 8 : 0);
    const int v_cb = (lane & 16) ? 16 : 0;

    const int ntiles = (q0 >> 6) + 2;

#pragma unroll 1
    for (int kt = 0; kt < ntiles; kt++) {
        const int buf = kt & 1;
        if (kt < ntiles - 1) {
            const int nb = buf ^ 1;
            const __half* kgn = kg + (size_t)(kt + 1) * 64 * 64;
            const __half* vgn = vg + (size_t)(kt + 1) * 64 * 64;
#pragma unroll
            for (int i = 0; i < 4; i++) {
                int idx = tid + i * 128, r = idx >> 3, ch = idx & 7;
                cpa16(sK0 + nb * KVSZ + r * 144 + ch * 16, kgn + r * 64 + ch * 8);
                cpa16(sV0 + nb * KVSZ + r * 144 + ch * 16, vgn + r * 64 + ch * 8);
            }
            asm volatile("cp.async.commit_group;");
            asm volatile("cp.async.wait_group 1;");
        } else {
            asm volatile("cp.async.wait_group 0;");
        }
        __syncthreads();

        const uint32_t sk = sK0 + buf * KVSZ;
        const uint32_t sv = sV0 + buf * KVSZ;

        float accS[2][8][4];
#pragma unroll
        for (int mi = 0; mi < 2; mi++)
#pragma unroll
            for (int ni = 0; ni < 8; ni++)
#pragma unroll
                for (int c = 0; c < 4; c++) accS[mi][ni][c] = 0.0f;

#pragma unroll
        for (int ks = 0; ks < 4; ks++) {
            uint32_t qa[2][4];
#pragma unroll
            for (int mi = 0; mi < 2; mi++)
                ldm4(qa[mi], sQ + (qrow_b + mi * 16) * 144 + ks * 32 + q_kb);
            uint32_t kb[8][2];
#pragma unroll
            for (int ni2 = 0; ni2 < 4; ni2++) {
                uint32_t r[4];
                ldm4(r, sk + (k_row + ni2 * 16) * 144 + ks * 32 + k_kb);
                kb[ni2 * 2 + 0][0] = r[0]; kb[ni2 * 2 + 0][1] = r[1];
                kb[ni2 * 2 + 1][0] = r[2]; kb[ni2 * 2 + 1][1] = r[3];
            }
#pragma unroll
            for (int mi = 0; mi < 2; mi++)
#pragma unroll
                for (int ni = 0; ni < 8; ni++)
                    mma16816(accS[mi][ni], qa[mi], kb[ni]);
        }

        const int k0 = kt * 64;
        if (k0 + 63 > q0) {
            const int row0 = q0 + wid * 32 + (lane >> 2);
            const int colb = k0 + (lane & 3) * 2;
#pragma unroll
            for (int mi = 0; mi < 2; mi++)
#pragma unroll
                for (int ni = 0; ni < 8; ni++) {
                    const int kkb = colb + ni * 8;
                    const int rlo = row0 + mi * 16, rhi = rlo + 8;
                    if (kkb > rlo)     accS[mi][ni][0] = -1e30f;
                    if (kkb + 1 > rlo) accS[mi][ni][1] = -1e30f;
                    if (kkb > rhi)     accS[mi][ni][2] = -1e30f;
                    if (kkb + 1 > rhi) accS[mi][ni][3] = -1e30f;
                }
        }

#pragma unroll
        for (int mi = 0; mi < 2; mi++) {
            float mx0 = -1e30f, mx1 = -1e30f;
#pragma unroll
            for (int ni = 0; ni < 8; ni++) {
                mx0 = fmaxf(mx0, fmaxf(accS[mi][ni][0], accS[mi][ni][1]));
                mx1 = fmaxf(mx1, fmaxf(accS[mi][ni][2], accS[mi][ni][3]));
            }
            mx0 = fmaxf(mx0, __shfl_xor_sync(0xffffffff, mx0, 1));
            mx0 = fmaxf(mx0, __shfl_xor_sync(0xffffffff, mx0, 2));
            mx1 = fmaxf(mx1, __shfl_xor_sync(0xffffffff, mx1, 1));
            mx1 = fmaxf(mx1, __shfl_xor_sync(0xffffffff, mx1, 2));

            const float mn0 = fmaxf(mrow[mi][0], mx0);
            const float mn1 = fmaxf(mrow[mi][1], mx1);
            const float cor0 = ex2f(mrow[mi][0] - mn0);
            const float cor1 = ex2f(mrow[mi][1] - mn1);
            mrow[mi][0] = mn0; mrow[mi][1] = mn1;

            float sum0 = 0.0f, sum1 = 0.0f;
#pragma unroll
            for (int ni = 0; ni < 8; ni++) {
                float p0 = ex2f(accS[mi][ni][0] - mn0);
                float p1 = ex2f(accS[mi][ni][1] - mn0);
                float p2 = ex2f(accS[mi][ni][2] - mn1);
                float p3 = ex2f(accS[mi][ni][3] - mn1);
                accS[mi][ni][0] = p0; accS[mi][ni][1] = p1;
                accS[mi][ni][2] = p2; accS[mi][ni][3] = p3;
                sum0 += p0 + p1; sum1 += p2 + p3;
                accO[mi][ni][0] *= cor0; accO[mi][ni][1] *= cor0;
                accO[mi][ni][2] *= cor1; accO[mi][ni][3] *= cor1;
            }
            sum0 += __shfl_xor_sync(0xffffffff, sum0, 1);
            sum0 += __shfl_xor_sync(0xffffffff, sum0, 2);
            sum1 += __shfl_xor_sync(0xffffffff, sum1, 1);
            sum1 += __shfl_xor_sync(0xffffffff, sum1, 2);
            lrow[mi][0] = lrow[mi][0] * cor0 + sum0;
            lrow[mi][1] = lrow[mi][1] * cor1 + sum1;
        }

#pragma unroll
        for (int ks = 0; ks < 4; ks++) {
            uint32_t vb[8][2];
#pragma unroll
            for (int ni2 = 0; ni2 < 4; ni2++) {
                uint32_t r[4];
                ldm4t(r, sv + (ks * 16 + v_row) * 144 + ni2 * 32 + v_cb);
                vb[ni2 * 2 + 0][0] = r[0]; vb[ni2 * 2 + 0][1] = r[1];
                vb[ni2 * 2 + 1][0] = r[2]; vb[ni2 * 2 + 1][1] = r[3];
            }
#pragma unroll
            for (int mi = 0; mi < 2; mi++) {
                uint32_t pa[4];
                __half2 t0 = __floats2half2_rn(accS[mi][2 * ks][0], accS[mi][2 * ks][1]);
                __half2 t1 = __floats2half2_rn(accS[mi][2 * ks][2], accS[mi][2 * ks][3]);
                __half2 t2 = __floats2half2_rn(accS[mi][2 * ks + 1][0], accS[mi][2 * ks + 1][1]);
                __half2 t3 = __floats2half2_rn(accS[mi][2 * ks + 1][2], accS[mi][2 * ks + 1][3]);
                pa[0] = *reinterpret_cast<uint32_t*>(&t0);
                pa[1] = *reinterpret_cast<uint32_t*>(&t1);
                pa[2] = *reinterpret_cast<uint32_t*>(&t2);
                pa[3] = *reinterpret_cast<uint32_t*>(&t3);
#pragma unroll
                for (int ni = 0; ni < 8; ni++)
                    mma16816(accO[mi][ni], pa, vb[ni]);
            }
        }
        __syncthreads();
    }

    const int b = bh >> 4, h = bh & 15;
#pragma unroll
    for (int mi = 0; mi < 2; mi++) {
        const float inv0 = 1.0f / lrow[mi][0];
        const float inv1 = 1.0f / lrow[mi][1];
        const int rlo = q0 + wid * 32 + mi * 16 + (lane >> 2);
#pragma unroll
        for (int ni = 0; ni < 8; ni++) {
            const int col = h * HDz + ni * 8 + (lane & 3) * 2;
            *reinterpret_cast<__half2*>(
                &g_att_h[((size_t)b * Tz + rlo) * Cz + col]) =
                __floats2half2_rn(accO[mi][ni][0] * inv0, accO[mi][ni][1] * inv0);
            *reinterpret_cast<__half2*>(
                &g_att_h[((size_t)b * Tz + rlo + 8) * Cz + col]) =
                __floats2half2_rn(accO[mi][ni][2] * inv1, accO[mi][ni][3] * inv1);
        }
    }
}

// ---------------------------------------------------------------------------
extern "C" void kernel_launch(void* const* d_in, const int* in_sizes, int n_in,
                              void* d_out, int out_size) {
    const float* x      = (const float*)d_in[0];
    const float* W_attn = (const float*)d_in[1];
    const float* b_attn = (const float*)d_in[2];
    const float* W_proj = (const float*)d_in[3];
    const float* b_proj = (const float*)d_in[4];
    float* out = (float*)d_out;
    (void)in_sizes; (void)n_in; (void)out_size;

    __half* xh;  cudaGetSymbolAddress((void**)&xh,  g_xh);
    __half* wat; cudaGetSymbolAddress((void**)&wat, g_wat);
    __half* wpt; cudaGetSymbolAddress((void**)&wpt, g_wpt);
    __half* ath; cudaGetSymbolAddress((void**)&ath, g_att_h);

    cudaFuncSetAttribute(gemm_mma, cudaFuncAttributeMaxDynamicSharedMemorySize, GEMM_SMEM);
    cudaFuncSetAttribute(attn_mma, cudaFuncAttributeMaxDynamicSharedMemorySize, ATT_SMEM);

    {
        int n4 = Mz * Cz / 4;
        conv_x_kernel<<<(n4 + 255) / 256, 256>>>((const float4*)x, (uint2*)xh, n4);
        dim3 g(3 * Cz / 32, Cz / 32);
        convT_kernel<<<g, dim3(32, 8)>>>(W_attn, wat, Cz, 3 * Cz);
        dim3 g2(Cz / 32, Cz / 32);
        convT_kernel<<<g2, dim3(32, 8)>>>(W_proj, wpt, Cz, Cz);
    }

    dim3 g1(3 * Cz / 128, Mz / 128);
    gemm_mma<<<g1, 128, GEMM_SMEM>>>(xh, wat, b_attn, nullptr, 3 * Cz, 0);

    dim3 g2(Tz / 128, Bz * Hz);
    attn_mma<<<g2, 128, ATT_SMEM>>>();

    dim3 g3(Cz / 128, Mz / 128);
    gemm_mma<<<g3, 128, GEMM_SMEM>>>(ath, wpt, b_proj, out, Cz, 1);
}

// round 7
// speedup vs baseline: 9.2992x; 1.0478x over previous
#include <cuda_runtime.h>
#include <cuda_fp16.h>
#include <math.h>
#include <stdint.h>

#define Bz 4
#define Tz 2048
#define Cz 1024
#define Hz 16
#define HDz 64
#define Mz (Bz * Tz)

#define QSCALE 0.1803368801111204f   // 1/sqrt(64) * log2(e)

// ---------------- scratch ----------------------------------------------------
__device__ __half g_qh[(size_t)Bz * Hz * Tz * HDz];
__device__ __half g_kh[(size_t)Bz * Hz * Tz * HDz];
__device__ __half g_vh[(size_t)Bz * Hz * Tz * HDz];
__device__ __half g_xh[(size_t)Mz * Cz];
__device__ __half g_wat[(size_t)3 * Cz * Cz];
__device__ __half g_wpt[(size_t)Cz * Cz];
__device__ __half g_att_h[(size_t)Mz * Cz];

// ---------------- helpers ----------------------------------------------------
static __device__ __forceinline__ uint32_t s2u(const void* p) {
    uint32_t a;
    asm("{ .reg .u64 t; cvta.to.shared.u64 t, %1; cvt.u32.u64 %0, t; }"
        : "=r"(a) : "l"(p));
    return a;
}

static __device__ __forceinline__ void cpa16(uint32_t dst, const void* src) {
    asm volatile("cp.async.cg.shared.global [%0], [%1], 16;"
                 :: "r"(dst), "l"(__cvta_generic_to_global(src)));
}

static __device__ __forceinline__ void ldm4(uint32_t* r, uint32_t addr) {
    asm volatile("ldmatrix.sync.aligned.m8n8.x4.shared.b16 {%0,%1,%2,%3}, [%4];"
                 : "=r"(r[0]), "=r"(r[1]), "=r"(r[2]), "=r"(r[3]) : "r"(addr));
}

static __device__ __forceinline__ void ldm4t(uint32_t* r, uint32_t addr) {
    asm volatile("ldmatrix.sync.aligned.m8n8.x4.trans.shared.b16 {%0,%1,%2,%3}, [%4];"
                 : "=r"(r[0]), "=r"(r[1]), "=r"(r[2]), "=r"(r[3]) : "r"(addr));
}

static __device__ __forceinline__ void mma16816(float* c, const uint32_t* a,
                                                const uint32_t* b) {
    asm volatile(
        "mma.sync.aligned.m16n8k16.row.col.f32.f16.f16.f32 "
        "{%0,%1,%2,%3}, {%4,%5,%6,%7}, {%8,%9}, {%0,%1,%2,%3};"
        : "+f"(c[0]), "+f"(c[1]), "+f"(c[2]), "+f"(c[3])
        : "r"(a[0]), "r"(a[1]), "r"(a[2]), "r"(a[3]), "r"(b[0]), "r"(b[1]));
}

static __device__ __forceinline__ float ex2f(float x) {
    float y;
    asm("ex2.approx.ftz.f32 %0, %1;" : "=f"(y) : "f"(x));
    return y;
}

// ---------------- conversion kernels ----------------------------------------
__global__ void conv_x_kernel(const float4* __restrict__ x, uint2* __restrict__ xh, int n4) {
    int i = blockIdx.x * blockDim.x + threadIdx.x;
    if (i < n4) {
        float4 v = x[i];
        __half2 h0 = __floats2half2_rn(v.x, v.y);
        __half2 h1 = __floats2half2_rn(v.z, v.w);
        uint2 u;
        u.x = *reinterpret_cast<uint32_t*>(&h0);
        u.y = *reinterpret_cast<uint32_t*>(&h1);
        xh[i] = u;
    }
}

__global__ void convT_kernel(const float* __restrict__ W, __half* __restrict__ Wt,
                             int R, int C) {
    __shared__ float t[32][33];
    int c0 = blockIdx.x * 32, r0 = blockIdx.y * 32;
    int tx = threadIdx.x, ty = threadIdx.y;
#pragma unroll
    for (int i = 0; i < 4; i++)
        t[ty + i * 8][tx] = W[(size_t)(r0 + ty + i * 8) * C + c0 + tx];
    __syncthreads();
#pragma unroll
    for (int i = 0; i < 4; i++)
        Wt[(size_t)(c0 + ty + i * 8) * R + r0 + tx] = __float2half_rn(t[tx][ty + i * 8]);
}

// ---------------- mma.sync fp16 GEMM: 4 warps, 64x64, frag double-buffer ------
#define NSTAGE 4
#define STG_B 20480            // A (10240B) + B (10240B) per stage
#define GEMM_SMEM (NSTAGE * STG_B)

__global__ __launch_bounds__(128, 2) void gemm_mma(
    const __half* __restrict__ Ah, const __half* __restrict__ Bh,
    const float* __restrict__ bias, float* __restrict__ out,
    int N, int mode) {
    extern __shared__ __align__(16) char gsm[];
    const uint32_t s_base = s2u(gsm);

    const int tid = threadIdx.x;
    const int wid = tid >> 5, lane = tid & 31;
    const int warp_m = wid & 1, warp_n = wid >> 1;
    const int m0 = blockIdx.y * 128, n0 = blockIdx.x * 128;

    float acc[4][8][4];
#pragma unroll
    for (int mi = 0; mi < 4; mi++)
#pragma unroll
        for (int ni = 0; ni < 8; ni++)
#pragma unroll
            for (int c = 0; c < 4; c++) acc[mi][ni][c] = 0.0f;

    const int lrow = tid >> 2;
    const int lcol = (tid & 3) * 16;
    const int gcol = (tid & 3) * 8;

    const int a_row = warp_m * 64 + (lane & 15);
    const int a_kb = (lane >> 4) * 16;
    const int b_row_base = warp_n * 64 + (lane & 7) + ((lane & 16) ? 8 : 0);
    const int b_kb = (lane & 8) ? 16 : 0;

    // prologue: stages 0..2
#pragma unroll
    for (int s = 0; s < NSTAGE - 1; s++) {
        const int k0 = s * 32;
        const uint32_t sa = s_base + s * STG_B;
#pragma unroll
        for (int i = 0; i < 4; i++) {
            const int r = lrow + i * 32;
            cpa16(sa + r * 80 + lcol, Ah + (size_t)(m0 + r) * 1024 + k0 + gcol);
            cpa16(sa + 10240 + r * 80 + lcol, Bh + (size_t)(n0 + r) * 1024 + k0 + gcol);
        }
        asm volatile("cp.async.commit_group;");
    }

    uint32_t af[2][4][4];
    uint32_t bf[2][8][2];

    // frag load macro: buffer fi <- stage base saddr, k-step byte offset kb
#define LOADF(fi, saddr, kb)                                                    \
    do {                                                                        \
        const uint32_t _sa = (saddr);                                           \
        const uint32_t _sb = _sa + 10240;                                       \
        _Pragma("unroll")                                                       \
        for (int mi = 0; mi < 4; mi++)                                          \
            ldm4(af[fi][mi], _sa + (a_row + mi * 16) * 80 + (kb) + a_kb);       \
        _Pragma("unroll")                                                       \
        for (int ni2 = 0; ni2 < 4; ni2++) {                                     \
            uint32_t _r[4];                                                     \
            ldm4(_r, _sb + (b_row_base + ni2 * 16) * 80 + (kb) + b_kb);         \
            bf[fi][ni2 * 2 + 0][0] = _r[0]; bf[fi][ni2 * 2 + 0][1] = _r[1];     \
            bf[fi][ni2 * 2 + 1][0] = _r[2]; bf[fi][ni2 * 2 + 1][1] = _r[3];     \
        }                                                                       \
    } while (0)

#define MMAALL(fi)                                                              \
    do {                                                                        \
        _Pragma("unroll")                                                       \
        for (int mi = 0; mi < 4; mi++)                                          \
            _Pragma("unroll")                                                   \
            for (int ni = 0; ni < 8; ni++)                                      \
                mma16816(acc[mi][ni], af[fi][mi], bf[fi][ni]);                  \
    } while (0)

    // chunk 0 ready
    asm volatile("cp.async.wait_group %0;" :: "n"(NSTAGE - 2));
    __syncthreads();
    LOADF(0, s_base, 0);

#pragma unroll 1
    for (int kc = 0; kc < 32; kc++) {
        const uint32_t scur = s_base + (kc & (NSTAGE - 1)) * STG_B;

        // prefetch ks=1 frags of this chunk
        LOADF(1, scur, 32);

        // issue global loads for stage kc+3 (empty group if past end)
        if (kc + NSTAGE - 1 < 32) {
            const int s = (kc + NSTAGE - 1) & (NSTAGE - 1);
            const int k0 = (kc + NSTAGE - 1) * 32;
            const uint32_t sa = s_base + s * STG_B;
#pragma unroll
            for (int i = 0; i < 4; i++) {
                const int r = lrow + i * 32;
                cpa16(sa + r * 80 + lcol, Ah + (size_t)(m0 + r) * 1024 + k0 + gcol);
                cpa16(sa + 10240 + r * 80 + lcol, Bh + (size_t)(n0 + r) * 1024 + k0 + gcol);
            }
        }
        asm volatile("cp.async.commit_group;");

        // MMAs for ks=0 (frags loaded last iteration / before loop)
        MMAALL(0);

        if (kc < 31) {
            // make chunk kc+1 visible, then prefetch its ks=0 frags
            asm volatile("cp.async.wait_group %0;" :: "n"(NSTAGE - 2));
            __syncthreads();
            LOADF(0, s_base + ((kc + 1) & (NSTAGE - 1)) * STG_B, 0);
        }

        // MMAs for ks=1
        MMAALL(1);
    }
#undef LOADF
#undef MMAALL

    const int rbase = warp_m * 64 + (lane >> 2);
    const int cbase = warp_n * 64 + (lane & 3) * 2;
#pragma unroll
    for (int mi = 0; mi < 4; mi++) {
#pragma unroll
        for (int ni = 0; ni < 8; ni++) {
            const int n = n0 + cbase + ni * 8;
            const float2 bsv = *reinterpret_cast<const float2*>(&bias[n]);
#pragma unroll
            for (int hh = 0; hh < 2; hh++) {
                const int m = m0 + rbase + mi * 16 + hh * 8;
                float vx = acc[mi][ni][hh * 2 + 0] + bsv.x;
                float vy = acc[mi][ni][hh * 2 + 1] + bsv.y;
                if (mode == 0) {
                    const int which = n >> 10;
                    const int ci = n & 1023;
                    const int h = ci >> 6, d = ci & 63;
                    const int b = m >> 11, t = m & 2047;
                    if (which == 0) { vx *= QSCALE; vy *= QSCALE; }
                    __half* dst = (which == 0) ? g_qh : (which == 1) ? g_kh : g_vh;
                    *reinterpret_cast<__half2*>(
                        &dst[(((size_t)b * Hz + h) * Tz + t) * HDz + d]) =
                        __floats2half2_rn(vx, vy);
                } else {
                    float2 v; v.x = vx; v.y = vy;
                    *reinterpret_cast<float2*>(&out[(size_t)m * N + n]) = v;
                }
            }
        }
    }
}

// ---------------- flash attention: mma.sync fp16 ------------------------------
#define ATT_SMEM 55296
#define KVSZ 9216

__global__ __launch_bounds__(128) void attn_mma() {
    extern __shared__ __align__(16) char sm[];
    const uint32_t sQ = s2u(sm);
    const uint32_t sK0 = sQ + 128 * 144;
    const uint32_t sV0 = sK0 + 2 * KVSZ;

    const int tid = threadIdx.x, lane = tid & 31, wid = tid >> 5;
    const int bh = blockIdx.y;
    const int q0 = ((int)gridDim.x - 1 - (int)blockIdx.x) * 128;

    const __half* qg = g_qh + ((size_t)bh * Tz + q0) * HDz;
    const __half* kg = g_kh + (size_t)bh * Tz * HDz;
    const __half* vg = g_vh + (size_t)bh * Tz * HDz;

    {
#pragma unroll
        for (int i = 0; i < 8; i++) {
            int idx = tid + i * 128, r = idx >> 3, ch = idx & 7;
            cpa16(sQ + r * 144 + ch * 16, qg + r * 64 + ch * 8);
        }
#pragma unroll
        for (int i = 0; i < 4; i++) {
            int idx = tid + i * 128, r = idx >> 3, ch = idx & 7;
            cpa16(sK0 + r * 144 + ch * 16, kg + r * 64 + ch * 8);
            cpa16(sV0 + r * 144 + ch * 16, vg + r * 64 + ch * 8);
        }
        asm volatile("cp.async.commit_group;");
    }

    float accO[2][8][4];
#pragma unroll
    for (int mi = 0; mi < 2; mi++)
#pragma unroll
        for (int ni = 0; ni < 8; ni++)
#pragma unroll
            for (int c = 0; c < 4; c++) accO[mi][ni][c] = 0.0f;
    float mrow[2][2] = { {-1e30f, -1e30f}, {-1e30f, -1e30f} };
    float lrow[2][2] = { {0.0f, 0.0f}, {0.0f, 0.0f} };

    const int qrow_b = wid * 32 + (lane & 15);
    const int q_kb = (lane >> 4) * 16;
    const int k_row = (lane & 7) + ((lane & 16) ? 8 : 0);
    const int k_kb = (lane & 8) ? 16 : 0;
    const int v_row = (lane & 7) + ((lane & 8) ? 8 : 0);
    const int v_cb = (lane & 16) ? 16 : 0;

    const int ntiles = (q0 >> 6) + 2;

#pragma unroll 1
    for (int kt = 0; kt < ntiles; kt++) {
        const int buf = kt & 1;
        if (kt < ntiles - 1) {
            const int nb = buf ^ 1;
            const __half* kgn = kg + (size_t)(kt + 1) * 64 * 64;
            const __half* vgn = vg + (size_t)(kt + 1) * 64 * 64;
#pragma unroll
            for (int i = 0; i < 4; i++) {
                int idx = tid + i * 128, r = idx >> 3, ch = idx & 7;
                cpa16(sK0 + nb * KVSZ + r * 144 + ch * 16, kgn + r * 64 + ch * 8);
                cpa16(sV0 + nb * KVSZ + r * 144 + ch * 16, vgn + r * 64 + ch * 8);
            }
            asm volatile("cp.async.commit_group;");
            asm volatile("cp.async.wait_group 1;");
        } else {
            asm volatile("cp.async.wait_group 0;");
        }
        __syncthreads();

        const uint32_t sk = sK0 + buf * KVSZ;
        const uint32_t sv = sV0 + buf * KVSZ;

        float accS[2][8][4];
#pragma unroll
        for (int mi = 0; mi < 2; mi++)
#pragma unroll
            for (int ni = 0; ni < 8; ni++)
#pragma unroll
                for (int c = 0; c < 4; c++) accS[mi][ni][c] = 0.0f;

#pragma unroll
        for (int ks = 0; ks < 4; ks++) {
            uint32_t qa[2][4];
#pragma unroll
            for (int mi = 0; mi < 2; mi++)
                ldm4(qa[mi], sQ + (qrow_b + mi * 16) * 144 + ks * 32 + q_kb);
            uint32_t kb[8][2];
#pragma unroll
            for (int ni2 = 0; ni2 < 4; ni2++) {
                uint32_t r[4];
                ldm4(r, sk + (k_row + ni2 * 16) * 144 + ks * 32 + k_kb);
                kb[ni2 * 2 + 0][0] = r[0]; kb[ni2 * 2 + 0][1] = r[1];
                kb[ni2 * 2 + 1][0] = r[2]; kb[ni2 * 2 + 1][1] = r[3];
            }
#pragma unroll
            for (int mi = 0; mi < 2; mi++)
#pragma unroll
                for (int ni = 0; ni < 8; ni++)
                    mma16816(accS[mi][ni], qa[mi], kb[ni]);
        }

        const int k0 = kt * 64;
        if (k0 + 63 > q0) {
            const int row0 = q0 + wid * 32 + (lane >> 2);
            const int colb = k0 + (lane & 3) * 2;
#pragma unroll
            for (int mi = 0; mi < 2; mi++)
#pragma unroll
                for (int ni = 0; ni < 8; ni++) {
                    const int kkb = colb + ni * 8;
                    const int rlo = row0 + mi * 16, rhi = rlo + 8;
                    if (kkb > rlo)     accS[mi][ni][0] = -1e30f;
                    if (kkb + 1 > rlo) accS[mi][ni][1] = -1e30f;
                    if (kkb > rhi)     accS[mi][ni][2] = -1e30f;
                    if (kkb + 1 > rhi) accS[mi][ni][3] = -1e30f;
                }
        }

#pragma unroll
        for (int mi = 0; mi < 2; mi++) {
            float mx0 = -1e30f, mx1 = -1e30f;
#pragma unroll
            for (int ni = 0; ni < 8; ni++) {
                mx0 = fmaxf(mx0, fmaxf(accS[mi][ni][0], accS[mi][ni][1]));
                mx1 = fmaxf(mx1, fmaxf(accS[mi][ni][2], accS[mi][ni][3]));
            }
            mx0 = fmaxf(mx0, __shfl_xor_sync(0xffffffff, mx0, 1));
            mx0 = fmaxf(mx0, __shfl_xor_sync(0xffffffff, mx0, 2));
            mx1 = fmaxf(mx1, __shfl_xor_sync(0xffffffff, mx1, 1));
            mx1 = fmaxf(mx1, __shfl_xor_sync(0xffffffff, mx1, 2));

            const float mn0 = fmaxf(mrow[mi][0], mx0);
            const float mn1 = fmaxf(mrow[mi][1], mx1);
            const float cor0 = ex2f(mrow[mi][0] - mn0);
            const float cor1 = ex2f(mrow[mi][1] - mn1);
            mrow[mi][0] = mn0; mrow[mi][1] = mn1;

            float sum0 = 0.0f, sum1 = 0.0f;
#pragma unroll
            for (int ni = 0; ni < 8; ni++) {
                float p0 = ex2f(accS[mi][ni][0] - mn0);
                float p1 = ex2f(accS[mi][ni][1] - mn0);
                float p2 = ex2f(accS[mi][ni][2] - mn1);
                float p3 = ex2f(accS[mi][ni][3] - mn1);
                accS[mi][ni][0] = p0; accS[mi][ni][1] = p1;
                accS[mi][ni][2] = p2; accS[mi][ni][3] = p3;
                sum0 += p0 + p1; sum1 += p2 + p3;
                accO[mi][ni][0] *= cor0; accO[mi][ni][1] *= cor0;
                accO[mi][ni][2] *= cor1; accO[mi][ni][3] *= cor1;
            }
            sum0 += __shfl_xor_sync(0xffffffff, sum0, 1);
            sum0 += __shfl_xor_sync(0xffffffff, sum0, 2);
            sum1 += __shfl_xor_sync(0xffffffff, sum1, 1);
            sum1 += __shfl_xor_sync(0xffffffff, sum1, 2);
            lrow[mi][0] = lrow[mi][0] * cor0 + sum0;
            lrow[mi][1] = lrow[mi][1] * cor1 + sum1;
        }

#pragma unroll
        for (int ks = 0; ks < 4; ks++) {
            uint32_t vb[8][2];
#pragma unroll
            for (int ni2 = 0; ni2 < 4; ni2++) {
                uint32_t r[4];
                ldm4t(r, sv + (ks * 16 + v_row) * 144 + ni2 * 32 + v_cb);
                vb[ni2 * 2 + 0][0] = r[0]; vb[ni2 * 2 + 0][1] = r[1];
                vb[ni2 * 2 + 1][0] = r[2]; vb[ni2 * 2 + 1][1] = r[3];
            }
#pragma unroll
            for (int mi = 0; mi < 2; mi++) {
                uint32_t pa[4];
                __half2 t0 = __floats2half2_rn(accS[mi][2 * ks][0], accS[mi][2 * ks][1]);
                __half2 t1 = __floats2half2_rn(accS[mi][2 * ks][2], accS[mi][2 * ks][3]);
                __half2 t2 = __floats2half2_rn(accS[mi][2 * ks + 1][0], accS[mi][2 * ks + 1][1]);
                __half2 t3 = __floats2half2_rn(accS[mi][2 * ks + 1][2], accS[mi][2 * ks + 1][3]);
                pa[0] = *reinterpret_cast<uint32_t*>(&t0);
                pa[1] = *reinterpret_cast<uint32_t*>(&t1);
                pa[2] = *reinterpret_cast<uint32_t*>(&t2);
                pa[3] = *reinterpret_cast<uint32_t*>(&t3);
#pragma unroll
                for (int ni = 0; ni < 8; ni++)
                    mma16816(accO[mi][ni], pa, vb[ni]);
            }
        }
        __syncthreads();
    }

    const int b = bh >> 4, h = bh & 15;
#pragma unroll
    for (int mi = 0; mi < 2; mi++) {
        const float inv0 = 1.0f / lrow[mi][0];
        const float inv1 = 1.0f / lrow[mi][1];
        const int rlo = q0 + wid * 32 + mi * 16 + (lane >> 2);
#pragma unroll
        for (int ni = 0; ni < 8; ni++) {
            const int col = h * HDz + ni * 8 + (lane & 3) * 2;
            *reinterpret_cast<__half2*>(
                &g_att_h[((size_t)b * Tz + rlo) * Cz + col]) =
                __floats2half2_rn(accO[mi][ni][0] * inv0, accO[mi][ni][1] * inv0);
            *reinterpret_cast<__half2*>(
                &g_att_h[((size_t)b * Tz + rlo + 8) * Cz + col]) =
                __floats2half2_rn(accO[mi][ni][2] * inv1, accO[mi][ni][3] * inv1);
        }
    }
}

// ---------------------------------------------------------------------------
extern "C" void kernel_launch(void* const* d_in, const int* in_sizes, int n_in,
                              void* d_out, int out_size) {
    const float* x      = (const float*)d_in[0];
    const float* W_attn = (const float*)d_in[1];
    const float* b_attn = (const float*)d_in[2];
    const float* W_proj = (const float*)d_in[3];
    const float* b_proj = (const float*)d_in[4];
    float* out = (float*)d_out;
    (void)in_sizes; (void)n_in; (void)out_size;

    __half* xh;  cudaGetSymbolAddress((void**)&xh,  g_xh);
    __half* wat; cudaGetSymbolAddress((void**)&wat, g_wat);
    __half* wpt; cudaGetSymbolAddress((void**)&wpt, g_wpt);
    __half* ath; cudaGetSymbolAddress((void**)&ath, g_att_h);

    cudaFuncSetAttribute(gemm_mma, cudaFuncAttributeMaxDynamicSharedMemorySize, GEMM_SMEM);
    cudaFuncSetAttribute(attn_mma, cudaFuncAttributeMaxDynamicSharedMemorySize, ATT_SMEM);

    {
        int n4 = Mz * Cz / 4;
        conv_x_kernel<<<(n4 + 255) / 256, 256>>>((const float4*)x, (uint2*)xh, n4);
        dim3 g(3 * Cz / 32, Cz / 32);
        convT_kernel<<<g, dim3(32, 8)>>>(W_attn, wat, Cz, 3 * Cz);
        dim3 g2(Cz / 32, Cz / 32);
        convT_kernel<<<g2, dim3(32, 8)>>>(W_proj, wpt, Cz, Cz);
    }

    dim3 g1(3 * Cz / 128, Mz / 128);
    gemm_mma<<<g1, 128, GEMM_SMEM>>>(xh, wat, b_attn, nullptr, 3 * Cz, 0);

    dim3 g2(Tz / 128, Bz * Hz);
    attn_mma<<<g2, 128, ATT_SMEM>>>();

    dim3 g3(Cz / 128, Mz / 128);
    gemm_mma<<<g3, 128, GEMM_SMEM>>>(ath, wpt, b_proj, out, Cz, 1);
}